// round 13
// baseline (speedup 1.0000x reference)
#include <cuda_runtime.h>
#include <cuda_bf16.h>
#include <math.h>

#define Bv 128
#define Tv 64
#define Cv 66
#define Sv 512
#define Wwin 32
#define G3 1536
#define TENC 63
#define NSTEP 127
#define BG3 (Bv * G3)

// dynamic smem layout (relative to 1024-aligned base)
#define OFF_WA 0              // weight slice A: 4 chunks x {hi 8K, lo 8K} = 64K
#define OFF_WB 65536          // weight slice B: 64K
#define OFF_AB 131072         // A-operand double buffer: 2 x 16K = 32K
#define OFF_GATE 163840       // gate1 scratch
#define SMEM_DYN (OFF_GATE + 2816 + 1024)

// ---------------- device scratch ----------------
__device__ float g_h0[Bv * Sv];
__device__ float g_h1[Bv * Sv];
__device__ float g_hist[NSTEP * Bv * Sv];
__device__ float g_gi0[TENC * BG3];
__device__ float g_gi0d[BG3];
__device__ float g_p_gh0[2][BG3];
__device__ float g_p_gh1[2][BG3];
__device__ float g_p_gi1[2][BG3];
__device__ float g_frame[Bv * Cv];
__device__ unsigned int g_arrive;

__device__ __nv_bfloat16 g_h0hi[Bv * Sv], g_h0lo[Bv * Sv];
__device__ __nv_bfloat16 g_h1hi[Bv * Sv], g_h1lo[Bv * Sv];
__device__ __nv_bfloat16 g_fhi[Bv * 128], g_flo[Bv * 128];
__device__ __nv_bfloat16 g_whh0hi[G3 * Sv], g_whh0lo[G3 * Sv];
__device__ __nv_bfloat16 g_whh1hi[G3 * Sv], g_whh1lo[G3 * Sv];
__device__ __nv_bfloat16 g_wih1hi[G3 * Sv], g_wih1lo[G3 * Sv];
__device__ __nv_bfloat16 g_w0hi[G3 * 128], g_w0lo[G3 * 128];

// ---------------- helpers ----------------
__device__ __forceinline__ unsigned smem_u32(const void *p) {
    unsigned a;
    asm("{ .reg .u64 t; cvta.to.shared.u64 t, %1; cvt.u32.u64 %0, t; }" : "=r"(a) : "l"(p));
    return a;
}
__device__ __forceinline__ void cpa16(unsigned dst, const void *src) {
    asm volatile("cp.async.cg.shared.global [%0], [%1], 16;" :: "r"(dst), "l"(src));
}
__device__ __forceinline__ void cpa_commit() {
    asm volatile("cp.async.commit_group;" ::: "memory");
}
template <int N> __device__ __forceinline__ void cpa_wait() {
    asm volatile("cp.async.wait_group %0;" :: "n"(N) : "memory");
}
#define LDSM4(R, addr) \
    asm volatile("ldmatrix.sync.aligned.m8n8.x4.shared.b16 {%0,%1,%2,%3}, [%4];" \
        : "=r"((R)[0]), "=r"((R)[1]), "=r"((R)[2]), "=r"((R)[3]) : "r"(addr))
#define MMA(D, A, b0, b1) \
    asm volatile("mma.sync.aligned.m16n8k16.row.col.f32.bf16.bf16.f32 " \
        "{%0,%1,%2,%3}, {%4,%5,%6,%7}, {%8,%9}, {%0,%1,%2,%3};" \
        : "+f"((D)[0]), "+f"((D)[1]), "+f"((D)[2]), "+f"((D)[3]) \
        : "r"((A)[0]), "r"((A)[1]), "r"((A)[2]), "r"((A)[3]), "r"(b0), "r"(b1))

__device__ __forceinline__ float sigf(float v) { return 1.f / (1.f + expf(-v)); }
__device__ __forceinline__ float4 ldcg4(const float *p) { return __ldcg((const float4 *)p); }
__device__ __forceinline__ float4 ldg4(const float *p) { return __ldg((const float4 *)p); }
__device__ __forceinline__ float4 add4(float4 a, float4 b) {
    return make_float4(a.x + b.x, a.y + b.y, a.z + b.z, a.w + b.w);
}
__device__ __forceinline__ void split_bf16(float v, __nv_bfloat16 &hi, __nv_bfloat16 &lo) {
    hi = __float2bfloat16(v);
    lo = __float2bfloat16(v - __bfloat162float(hi));
}

// ---------------- grid barrier (PROVEN single-counter) ----------------
__device__ __forceinline__ void gsync(unsigned &tgt, int nblk) {
    __syncthreads();
    tgt += (unsigned)nblk;
    if (threadIdx.x == 0) {
        __threadfence();
        atomicAdd(&g_arrive, 1u);
        while (*(volatile unsigned *)&g_arrive < tgt) { }
        __threadfence();
    }
    __syncthreads();
}

// ---------------- stage a 64x64 bf16 hi/lo tile pair via cp.async ----------
__device__ __forceinline__ void stage_tile64(unsigned dsthi, unsigned dstlo,
    const __nv_bfloat16 *__restrict__ hi, const __nv_bfloat16 *__restrict__ lo, int ld)
{
    const int t = threadIdx.x;
#pragma unroll
    for (int it = 0; it < 2; it++) {
        int idx = t + it * 256;
        int r = idx >> 3, c = idx & 7;
        unsigned off = (unsigned)(r * 128) + (unsigned)((c ^ (r & 7)) << 4);
        const int s = r * ld + c * 8;
        cpa16(dsthi + off, hi + s);
        cpa16(dstlo + off, lo + s);
    }
}

// ---------------- HMMA on one K=64 chunk ----------------
__device__ __forceinline__ void hmma_chunk(unsigned abuf, unsigned wbuf,
                                           int wm, int wn, int lane, float acc[2][2][4])
{
    const int lr = lane & 15;
    const int lh = lane >> 4;
#pragma unroll
    for (int ks = 0; ks < 4; ks++) {
        unsigned ah[2][4], al[2][4], bh[4], bl[4];
#pragma unroll
        for (int mt = 0; mt < 2; mt++) {
            int r = wm * 32 + mt * 16 + lr;
            unsigned ad = abuf + r * 128 + ((unsigned)((ks * 2 + lh) ^ (r & 7)) << 4);
            LDSM4(ah[mt], ad);
            LDSM4(al[mt], ad + 8192);
        }
        {
            int r = wn * 16 + lr;
            unsigned bd = wbuf + r * 128 + ((unsigned)((ks * 2 + lh) ^ (r & 7)) << 4);
            LDSM4(bh, bd);
            LDSM4(bl, bd + 8192);
        }
#pragma unroll
        for (int mt = 0; mt < 2; mt++) {
#pragma unroll
            for (int nt = 0; nt < 2; nt++) {
                unsigned h0 = nt ? bh[1] : bh[0], h1 = nt ? bh[3] : bh[2];
                unsigned l0 = nt ? bl[1] : bl[0], l1 = nt ? bl[3] : bl[2];
                MMA(acc[mt][nt], ah[mt], h0, h1);
                MMA(acc[mt][nt], ah[mt], l0, l1);
                MMA(acc[mt][nt], al[mt], h0, h1);
            }
        }
    }
}

__device__ __forceinline__ void epilogue(float acc[2][2][4], float *__restrict__ Out,
                                         int m0, int n0, int w, int lane)
{
    const int wm = w & 1, wn = w >> 1;
    const int r0 = m0 + wm * 32 + (lane >> 2);
    const int cb = n0 + wn * 16 + (lane & 3) * 2;
#pragma unroll
    for (int mt = 0; mt < 2; mt++)
#pragma unroll
        for (int nt = 0; nt < 2; nt++) {
            float *p = Out + (r0 + mt * 16) * G3 + cb + nt * 8;
            *(float2 *)p = make_float2(acc[mt][nt][0], acc[mt][nt][1]);
            *(float2 *)(p + 8 * G3) = make_float2(acc[mt][nt][2], acc[mt][nt][3]);
        }
}

// ---------------- 64x64x256 tile with persistent weights -------------------
__device__ void hmma_tile_p(
    const __nv_bfloat16 *__restrict__ Ahi, const __nv_bfloat16 *__restrict__ Alo,
    int m0, int k0, unsigned wbase, float *__restrict__ Out, int n0,
    unsigned sb)
{
    const int tid = threadIdx.x;
    const int lane = tid & 31;
    const int w = tid >> 5;
    const int wm = w & 1, wn = w >> 1;

    float acc[2][2][4];
#pragma unroll
    for (int a = 0; a < 2; a++)
#pragma unroll
        for (int b = 0; b < 2; b++)
#pragma unroll
            for (int c = 0; c < 4; c++) acc[a][b][c] = 0.f;

    const __nv_bfloat16 *a0 = Ahi + m0 * Sv + k0;
    const __nv_bfloat16 *a1 = Alo + m0 * Sv + k0;

    stage_tile64(sb + OFF_AB, sb + OFF_AB + 8192, a0, a1, Sv);
    cpa_commit();
#pragma unroll
    for (int ch = 0; ch < 4; ch++) {
        if (ch < 3) {
            unsigned nb = sb + OFF_AB + (unsigned)(((ch + 1) & 1) * 16384);
            stage_tile64(nb, nb + 8192, a0 + (ch + 1) * 64, a1 + (ch + 1) * 64, Sv);
            cpa_commit();
            cpa_wait<1>();
        } else {
            cpa_wait<0>();
        }
        __syncthreads();
        hmma_chunk(sb + OFF_AB + (unsigned)((ch & 1) * 16384),
                   wbase + (unsigned)(ch * 16384), wm, wn, lane, acc);
        __syncthreads();
    }
    epilogue(acc, Out, m0, n0, w, lane);
}

// ---------------- gi0d tile: K=128 (2 chunks) ----------------
__device__ void hmma_tile_gi0d(int m0, int n0, unsigned sb)
{
    const int tid = threadIdx.x;
    const int lane = tid & 31;
    const int w = tid >> 5;
    const int wm = w & 1, wn = w >> 1;

    float acc[2][2][4];
#pragma unroll
    for (int a = 0; a < 2; a++)
#pragma unroll
        for (int b = 0; b < 2; b++)
#pragma unroll
            for (int c = 0; c < 4; c++) acc[a][b][c] = 0.f;

#pragma unroll
    for (int ch = 0; ch < 2; ch++) {
        stage_tile64(sb + OFF_AB, sb + OFF_AB + 8192,
                     g_fhi + m0 * 128 + ch * 64, g_flo + m0 * 128 + ch * 64, 128);
        stage_tile64(sb + OFF_AB + 16384, sb + OFF_AB + 16384 + 8192,
                     g_w0hi + n0 * 128 + ch * 64, g_w0lo + n0 * 128 + ch * 64, 128);
        cpa_commit();
        cpa_wait<0>();
        __syncthreads();
        hmma_chunk(sb + OFF_AB, sb + OFF_AB + 16384, wm, wn, lane, acc);
        __syncthreads();
    }
    epilogue(acc, g_gi0d, m0, n0, w, lane);
}

// ---------------- gate1 for one batch row (whole block cooperates) ---------
__device__ void gate1_row(int sp, int b, char *dyn,
                          const float *__restrict__ bih1, const float *__restrict__ bhh1,
                          const float *__restrict__ Wt, const float *__restrict__ bt,
                          const float *__restrict__ Ws, const float *__restrict__ bs,
                          float *__restrict__ out)
{
    const int tid = threadIdx.x;
    const bool dec = (sp >= TENC);
    const int d = sp - TENC;
    float *shT = (float *)(dyn + OFF_GATE);
    float *shR = shT + 512;
    float *shWt = shR + 160;
    if (dec && tid < 32) shWt[tid] = __ldg(&Wt[tid]);
    __syncthreads();
    const float bt0 = __ldg(&bt[0]);

    for (int s = tid; s < Sv; s += 256) {
        const int rb = b * G3 + s;
        float ir = __ldg(&bih1[s]) + __ldcg(&g_p_gi1[0][rb]) + __ldcg(&g_p_gi1[1][rb]);
        float iz = __ldg(&bih1[512 + s]) + __ldcg(&g_p_gi1[0][rb + 512]) + __ldcg(&g_p_gi1[1][rb + 512]);
        float in_ = __ldg(&bih1[1024 + s]) + __ldcg(&g_p_gi1[0][rb + 1024]) + __ldcg(&g_p_gi1[1][rb + 1024]);
        float hr = __ldg(&bhh1[s]) + __ldcg(&g_p_gh1[0][rb]) + __ldcg(&g_p_gh1[1][rb]);
        float hz = __ldg(&bhh1[512 + s]) + __ldcg(&g_p_gh1[0][rb + 512]) + __ldcg(&g_p_gh1[1][rb + 512]);
        float hn = __ldg(&bhh1[1024 + s]) + __ldcg(&g_p_gh1[0][rb + 1024]) + __ldcg(&g_p_gh1[1][rb + 1024]);
        float r = sigf(ir + hr);
        float z = sigf(iz + hz);
        float n = tanhf(in_ + r * hn);
        float h1n = (1.f - z) * n + z * g_h1[b * Sv + s];
        g_h1[b * Sv + s] = h1n;
        g_hist[sp * (Bv * Sv) + b * Sv + s] = h1n;
        __nv_bfloat16 hh, hl;
        split_bf16(h1n, hh, hl);
        g_h1hi[b * Sv + s] = hh;
        g_h1lo[b * Sv + s] = hl;
        if (dec) {
            float acc = bt0;
            const float *hp = g_hist + b * Sv + s;
#pragma unroll
            for (int w = 0; w < Wwin - 1; w++)
                acc += shWt[w] * hp[(32 + d + w) * (Bv * Sv)];
            acc += shWt[Wwin - 1] * h1n;
            shT[s] = acc;
        }
    }
    if (dec) {
        __syncthreads();
        if (tid < 2 * Cv) {
            int c = tid >> 1, h = tid & 1;
            const float *wr = Ws + c * Sv + h * 256;
            const float *tr = shT + h * 256;
            float p0 = 0.f, p1 = 0.f, p2 = 0.f, p3 = 0.f;
#pragma unroll 4
            for (int s = 0; s < 256; s += 4) {
                p0 += tr[s + 0] * __ldg(&wr[s + 0]);
                p1 += tr[s + 1] * __ldg(&wr[s + 1]);
                p2 += tr[s + 2] * __ldg(&wr[s + 2]);
                p3 += tr[s + 3] * __ldg(&wr[s + 3]);
            }
            shR[tid] = (p0 + p1) + (p2 + p3);
        }
        __syncthreads();
        if (tid < Cv) {
            float ov = shR[2 * tid] + shR[2 * tid + 1] + __ldg(&bs[tid]);
            float nf = ov + g_frame[b * Cv + tid];
            out[b * (Tv * Cv) + d * Cv + tid] = nf;
            g_frame[b * Cv + tid] = nf;
            __nv_bfloat16 fh, fl;
            split_bf16(nf, fh, fl);
            g_fhi[b * 128 + tid] = fh;
            g_flo[b * 128 + tid] = fl;
        }
    }
    __syncthreads();
}

// ---------------- packed fp32x2 (pre_kernel GEMM) ----------------
__device__ __forceinline__ unsigned long long pack2(float a, float b) {
    unsigned long long r;
    asm("mov.b64 %0, {%1, %2};" : "=l"(r) : "f"(a), "f"(b));
    return r;
}
__device__ __forceinline__ unsigned long long ffma2(
    unsigned long long a, unsigned long long b, unsigned long long c) {
    unsigned long long d;
    asm("fma.rn.f32x2 %0, %1, %2, %3;" : "=l"(d) : "l"(a), "l"(b), "l"(c));
    return d;
}
union F2U { unsigned long long u; float2 f; };

// ---------------- kernel 1: init + encoder gi0 + weight conversions --------
__global__ void __launch_bounds__(256) pre_kernel(
    const float *__restrict__ x,
    const float *__restrict__ Wih0,
    const float *__restrict__ Whh0,
    const float *__restrict__ Whh1,
    const float *__restrict__ Wih1)
{
    __shared__ __align__(16) float shA[32 * 68];
    __shared__ __align__(16) float shW[32 * 68];
    const int tid = threadIdx.x;
    const int bx = blockIdx.x;

    if (bx < 64) {
        for (int i = bx * 256 + tid; i < Bv * Sv; i += 64 * 256) {
            g_h0[i] = 0.f; g_h1[i] = 0.f;
            __nv_bfloat16 z = __float2bfloat16(0.f);
            g_h0hi[i] = z; g_h0lo[i] = z; g_h1hi[i] = z; g_h1lo[i] = z;
        }
    }
    if (bx == 64) {
        for (int i = tid; i < Bv * 128; i += 256) {
            int b = i >> 7, c = i & 127;
            float v = (c < Cv) ? x[b * Tv * Cv + (Tv - 1) * Cv + c] : 0.f;
            __nv_bfloat16 hi, lo;
            split_bf16(v, hi, lo);
            g_fhi[i] = hi; g_flo[i] = lo;
            if (c < Cv) g_frame[b * Cv + c] = v;
        }
        if (tid == 0) g_arrive = 0u;
    }
    {
        const int NW = G3 * Sv;
        const int TOT = 3 * NW + G3 * 128;
        const int stride = gridDim.x * 256;
        for (int i = bx * 256 + tid; i < TOT; i += stride) {
            __nv_bfloat16 hi, lo;
            if (i < NW) {
                split_bf16(__ldg(&Whh0[i]), hi, lo);
                g_whh0hi[i] = hi; g_whh0lo[i] = lo;
            } else if (i < 2 * NW) {
                int j = i - NW;
                split_bf16(__ldg(&Whh1[j]), hi, lo);
                g_whh1hi[j] = hi; g_whh1lo[j] = lo;
            } else if (i < 3 * NW) {
                int j = i - 2 * NW;
                split_bf16(__ldg(&Wih1[j]), hi, lo);
                g_wih1hi[j] = hi; g_wih1lo[j] = lo;
            } else {
                int j = i - 3 * NW;
                int n = j >> 7, k = j & 127;
                float v = (k < Cv) ? __ldg(&Wih0[n * Cv + k]) : 0.f;
                split_bf16(v, hi, lo);
                g_w0hi[j] = hi; g_w0lo[j] = lo;
            }
        }
    }

    // encoder gi0 tile (fp32 full precision)
    const int rt = bx / 24;
    const int nt = bx % 24;
    const int r0 = rt * 64, n0 = nt * 64;
    const int tx = tid & 15, ty = tid >> 4;
    const int lr = tid >> 5, lc = tid & 31;

    unsigned long long acc2[4][2];
#pragma unroll
    for (int i = 0; i < 4; i++) { acc2[i][0] = 0ull; acc2[i][1] = 0ull; }

    for (int kc = 0; kc < Cv; kc += 32) {
        __syncthreads();
#pragma unroll
        for (int it = 0; it < 8; it++) {
            int r = lr + it * 8;
            int kk = kc + lc;
            float av = 0.f, wv = 0.f;
            if (kk < Cv) {
                int rr = r0 + r;
                int t = rr >> 7, b = rr & 127;
                av = __ldg(&x[b * (Tv * Cv) + t * Cv + kk]);
                wv = __ldg(&Wih0[(n0 + r) * Cv + kk]);
            }
            shA[lc * 68 + r] = av;
            shW[lc * 68 + r] = wv;
        }
        __syncthreads();
#pragma unroll
        for (int k = 0; k < 32; ++k) {
            const float4 avv = *(const float4 *)(shA + k * 68 + (ty << 2));
            const ulonglong2 bp = *(const ulonglong2 *)(shW + k * 68 + (tx << 2));
            const unsigned long long q0 = pack2(avv.x, avv.x);
            const unsigned long long q1 = pack2(avv.y, avv.y);
            const unsigned long long q2 = pack2(avv.z, avv.z);
            const unsigned long long q3 = pack2(avv.w, avv.w);
            acc2[0][0] = ffma2(q0, bp.x, acc2[0][0]);
            acc2[0][1] = ffma2(q0, bp.y, acc2[0][1]);
            acc2[1][0] = ffma2(q1, bp.x, acc2[1][0]);
            acc2[1][1] = ffma2(q1, bp.y, acc2[1][1]);
            acc2[2][0] = ffma2(q2, bp.x, acc2[2][0]);
            acc2[2][1] = ffma2(q2, bp.y, acc2[2][1]);
            acc2[3][0] = ffma2(q3, bp.x, acc2[3][0]);
            acc2[3][1] = ffma2(q3, bp.y, acc2[3][1]);
        }
    }
#pragma unroll
    for (int i = 0; i < 4; i++) {
        int rr = r0 + (ty << 2) + i;
        int t = rr >> 7, b = rr & 127;
        F2U u0, u1;
        u0.u = acc2[i][0]; u1.u = acc2[i][1];
        *(float4 *)(&g_gi0[t * BG3 + b * G3 + n0 + (tx << 2)]) =
            make_float4(u0.f.x, u0.f.y, u1.f.x, u1.f.y);
    }
}

// ---------------- kernel 2: persistent RNN, overlapped schedule -------------
__global__ void __launch_bounds__(256, 1) rnn_kernel(
    const float *__restrict__ bih0, const float *__restrict__ bhh0,
    const float *__restrict__ bih1, const float *__restrict__ bhh1,
    const float *__restrict__ Wt, const float *__restrict__ bt,
    const float *__restrict__ Ws, const float *__restrict__ bs,
    float *__restrict__ out, int nblk)
{
    extern __shared__ char dynraw[];
    char *dyn = (char *)(((unsigned long long)dynraw + 1023) & ~1023ull);
    const unsigned sb = smem_u32(dyn);

    const int bid = blockIdx.x;
    const int tid = threadIdx.x;
    unsigned tgt = 0;

    // ---- roles ----
    const bool do_gh0 = (bid < 96);
    const bool do_gh1 = (bid < 40) || (bid >= 96);
    const bool do_gi1 = (bid >= 40 && bid < 136);
    const bool do_g0  = (bid >= 40 && bid < 96);
    const bool do_g1  = (bid >= 96);

    const int gh0_kh = bid / 48, gh0_sub = bid % 48;
    const int gh0_m0 = (gh0_sub / 24) * 64, gh0_n0 = (gh0_sub % 24) * 64;

    const int gh1_task = (bid < 40) ? bid : 40 + (bid - 96);
    const int gh1_kh = gh1_task / 48, gh1_sub = gh1_task % 48;
    const int gh1_m0 = (gh1_sub / 24) * 64, gh1_n0 = (gh1_sub % 24) * 64;

    const int gi1_task = bid - 40;
    const int gi1_kh = gi1_task / 48, gi1_sub = gi1_task % 48;
    const int gi1_m0 = (gi1_sub / 24) * 64, gi1_n0 = (gi1_sub % 24) * 64;

    const unsigned gh1_wbuf = (bid < 40) ? (sb + OFF_WB) : (sb + OFF_WA);

    // ---- stage persistent weights (once) ----
    if (do_gh0) {
#pragma unroll
        for (int c = 0; c < 4; c++)
            stage_tile64(sb + OFF_WA + c * 16384, sb + OFF_WA + c * 16384 + 8192,
                         g_whh0hi + gh0_n0 * Sv + gh0_kh * 256 + c * 64,
                         g_whh0lo + gh0_n0 * Sv + gh0_kh * 256 + c * 64, Sv);
    } else if (do_gh1) {   // bid >= 96
#pragma unroll
        for (int c = 0; c < 4; c++)
            stage_tile64(sb + OFF_WA + c * 16384, sb + OFF_WA + c * 16384 + 8192,
                         g_whh1hi + gh1_n0 * Sv + gh1_kh * 256 + c * 64,
                         g_whh1lo + gh1_n0 * Sv + gh1_kh * 256 + c * 64, Sv);
    }
    if (bid < 40) {        // WB = gh1 slice
#pragma unroll
        for (int c = 0; c < 4; c++)
            stage_tile64(sb + OFF_WB + c * 16384, sb + OFF_WB + c * 16384 + 8192,
                         g_whh1hi + gh1_n0 * Sv + gh1_kh * 256 + c * 64,
                         g_whh1lo + gh1_n0 * Sv + gh1_kh * 256 + c * 64, Sv);
    } else if (do_gi1) {   // WB = gi1 slice
#pragma unroll
        for (int c = 0; c < 4; c++)
            stage_tile64(sb + OFF_WB + c * 16384, sb + OFF_WB + c * 16384 + 8192,
                         g_wih1hi + gi1_n0 * Sv + gi1_kh * 256 + c * 64,
                         g_wih1lo + gi1_n0 * Sv + gi1_kh * 256 + c * 64, Sv);
    }
    cpa_commit();
    cpa_wait<0>();
    __syncthreads();

    for (int step = 0; step < NSTEP; step++) {
        const bool dec = (step >= TENC);

        // ======== P1: gh0(step) [0..95]  ||  gate1(step-1) [96..151]
        if (do_gh0) {
            hmma_tile_p(g_h0hi, g_h0lo, gh0_m0, gh0_kh * 256, sb + OFF_WA,
                        g_p_gh0[gh0_kh], gh0_n0, sb);
        } else if (do_g1 && step > 0) {
            for (int r = bid - 96; r < Bv; r += 56)
                gate1_row(step - 1, r, dyn, bih1, bhh1, Wt, bt, Ws, bs, out);
        }
        gsync(tgt, nblk);

        // ======== P1.5 (decoder only): gi0d(step) [0..47]
        if (dec) {
            if (bid < 48)
                hmma_tile_gi0d((bid / 24) * 64, (bid % 24) * 64, sb);
            gsync(tgt, nblk);
        }

        // ======== P2: gate0(step) [40..95]  ||  gh1(step) [0..39, 96..151]
        if (do_gh1) {
            hmma_tile_p(g_h1hi, g_h1lo, gh1_m0, gh1_kh * 256, gh1_wbuf,
                        g_p_gh1[gh1_kh], gh1_n0, sb);
        } else if (do_g0) {
            const float *GI = dec ? g_gi0d : (g_gi0 + step * BG3);
            const int base = (bid - 40) * 256 + tid;
            const int stride = 56 * 256;
            for (int g = base; g < (Bv * Sv) / 4; g += stride) {
                int v = g << 2;
                int b = v >> 9, s = v & 511;
                const int rb = b * G3 + s;

                float4 ir = add4(ldcg4(GI + rb), ldg4(bih0 + s));
                float4 iz = add4(ldcg4(GI + rb + 512), ldg4(bih0 + 512 + s));
                float4 in_ = add4(ldcg4(GI + rb + 1024), ldg4(bih0 + 1024 + s));
                float4 hr = add4(add4(ldcg4(g_p_gh0[0] + rb), ldcg4(g_p_gh0[1] + rb)),
                                 ldg4(bhh0 + s));
                float4 hz = add4(add4(ldcg4(g_p_gh0[0] + rb + 512), ldcg4(g_p_gh0[1] + rb + 512)),
                                 ldg4(bhh0 + 512 + s));
                float4 hn = add4(add4(ldcg4(g_p_gh0[0] + rb + 1024), ldcg4(g_p_gh0[1] + rb + 1024)),
                                 ldg4(bhh0 + 1024 + s));
                float4 hold = ldcg4(g_h0 + v);

                float irv[4] = {ir.x, ir.y, ir.z, ir.w};
                float izv[4] = {iz.x, iz.y, iz.z, iz.w};
                float inv[4] = {in_.x, in_.y, in_.z, in_.w};
                float hrv[4] = {hr.x, hr.y, hr.z, hr.w};
                float hzv[4] = {hz.x, hz.y, hz.z, hz.w};
                float hnv[4] = {hn.x, hn.y, hn.z, hn.w};
                float hov[4] = {hold.x, hold.y, hold.z, hold.w};
                float res[4];
                __nv_bfloat16 rhi[4], rlo[4];
#pragma unroll
                for (int q = 0; q < 4; q++) {
                    float r = sigf(irv[q] + hrv[q]);
                    float z = sigf(izv[q] + hzv[q]);
                    float n = tanhf(inv[q] + r * hnv[q]);
                    res[q] = (1.f - z) * n + z * hov[q];
                    split_bf16(res[q], rhi[q], rlo[q]);
                }
                *(float4 *)(g_h0 + v) = make_float4(res[0], res[1], res[2], res[3]);
                __nv_bfloat162 *ph = (__nv_bfloat162 *)(g_h0hi + v);
                __nv_bfloat162 *pl = (__nv_bfloat162 *)(g_h0lo + v);
                ph[0] = __nv_bfloat162(rhi[0], rhi[1]);
                ph[1] = __nv_bfloat162(rhi[2], rhi[3]);
                pl[0] = __nv_bfloat162(rlo[0], rlo[1]);
                pl[1] = __nv_bfloat162(rlo[2], rlo[3]);
            }
        }
        gsync(tgt, nblk);

        // ======== P3: gi1(step) [40..135]
        if (do_gi1) {
            hmma_tile_p(g_h0hi, g_h0lo, gi1_m0, gi1_kh * 256, sb + OFF_WB,
                        g_p_gi1[gi1_kh], gi1_n0, sb);
        }
        gsync(tgt, nblk);
    }

    // ======== tail: gate1 for last step
    if (do_g1) {
        for (int r = bid - 96; r < Bv; r += 56)
            gate1_row(NSTEP - 1, r, dyn, bih1, bhh1, Wt, bt, Ws, bs, out);
    }
}

// ---------------- launch ----------------
extern "C" void kernel_launch(void *const *d_in, const int *in_sizes, int n_in,
                              void *d_out, int out_size)
{
    const float *x    = (const float *)d_in[0];
    const float *Wih0 = (const float *)d_in[1];
    const float *Whh0 = (const float *)d_in[2];
    const float *bih0 = (const float *)d_in[3];
    const float *bhh0 = (const float *)d_in[4];
    const float *Wih1 = (const float *)d_in[5];
    const float *Whh1 = (const float *)d_in[6];
    const float *bih1 = (const float *)d_in[7];
    const float *bhh1 = (const float *)d_in[8];
    const float *Wt   = (const float *)d_in[9];
    const float *bt   = (const float *)d_in[10];
    const float *Ws   = (const float *)d_in[11];
    const float *bs   = (const float *)d_in[12];
    float *out = (float *)d_out;

    int dev = 0;
    cudaGetDevice(&dev);
    int nsm = 0;
    cudaDeviceGetAttribute(&nsm, cudaDevAttrMultiProcessorCount, dev);
    if (nsm < 152) nsm = 152;

    cudaFuncSetAttribute(rnn_kernel, cudaFuncAttributeMaxDynamicSharedMemorySize, SMEM_DYN);

    pre_kernel<<<126 * 24, 256>>>(x, Wih0, Whh0, Whh1, Wih1);
    rnn_kernel<<<nsm, 256, SMEM_DYN>>>(bih0, bhh0, bih1, bhh1,
                                       Wt, bt, Ws, bs, out, nsm);
}

// round 14
// speedup vs baseline: 1.6877x; 1.6877x over previous
#include <cuda_runtime.h>
#include <cuda_bf16.h>
#include <math.h>

#define Bv 128
#define Tv 64
#define Cv 66
#define Sv 512
#define Wwin 32
#define G3 1536
#define TENC 63
#define NSTEP 127
#define BG3 (Bv * G3)

// dynamic smem layout (relative to 1024-aligned base)
#define OFF_WA 0              // phase-A weights: 4 chunks x {hi 8K, lo 8K} = 64K
#define OFF_WB 65536          // phase-B weights: 64K
#define OFF_AB 131072         // A-operand double buffer: 2 x 16K = 32K
#define OFF_GATE 163840       // gate1 scratch
#define SMEM_DYN (OFF_GATE + 2816 + 1024)

// ---------------- device scratch ----------------
__device__ float g_h0[Bv * Sv];
__device__ float g_h1[Bv * Sv];
__device__ float g_hist[NSTEP * Bv * Sv];
__device__ float g_gi0[TENC * BG3];
__device__ float g_gi0d[BG3];
__device__ float g_p_gh0[2][BG3];
__device__ float g_p_gh1[2][BG3];
__device__ float g_p_gi1[2][BG3];
__device__ float g_frame[Bv * Cv];
__device__ unsigned int g_arrive;
__device__ volatile unsigned int g_flag;

__device__ __nv_bfloat16 g_h0hi[Bv * Sv], g_h0lo[Bv * Sv];
__device__ __nv_bfloat16 g_h1hi[Bv * Sv], g_h1lo[Bv * Sv];
__device__ __nv_bfloat16 g_fhi[Bv * 128], g_flo[Bv * 128];
__device__ __nv_bfloat16 g_whh0hi[G3 * Sv], g_whh0lo[G3 * Sv];
__device__ __nv_bfloat16 g_whh1hi[G3 * Sv], g_whh1lo[G3 * Sv];
__device__ __nv_bfloat16 g_wih1hi[G3 * Sv], g_wih1lo[G3 * Sv];
__device__ __nv_bfloat16 g_w0hi[G3 * 128], g_w0lo[G3 * 128];

// ---------------- helpers ----------------
__device__ __forceinline__ unsigned smem_u32(const void *p) {
    unsigned a;
    asm("{ .reg .u64 t; cvta.to.shared.u64 t, %1; cvt.u32.u64 %0, t; }" : "=r"(a) : "l"(p));
    return a;
}
__device__ __forceinline__ void cpa16(unsigned dst, const void *src) {
    asm volatile("cp.async.cg.shared.global [%0], [%1], 16;" :: "r"(dst), "l"(src));
}
__device__ __forceinline__ void cpa_commit() {
    asm volatile("cp.async.commit_group;" ::: "memory");
}
template <int N> __device__ __forceinline__ void cpa_wait() {
    asm volatile("cp.async.wait_group %0;" :: "n"(N) : "memory");
}
#define LDSM4(R, addr) \
    asm volatile("ldmatrix.sync.aligned.m8n8.x4.shared.b16 {%0,%1,%2,%3}, [%4];" \
        : "=r"((R)[0]), "=r"((R)[1]), "=r"((R)[2]), "=r"((R)[3]) : "r"(addr))
#define MMA(D, A, b0, b1) \
    asm volatile("mma.sync.aligned.m16n8k16.row.col.f32.bf16.bf16.f32 " \
        "{%0,%1,%2,%3}, {%4,%5,%6,%7}, {%8,%9}, {%0,%1,%2,%3};" \
        : "+f"((D)[0]), "+f"((D)[1]), "+f"((D)[2]), "+f"((D)[3]) \
        : "r"((A)[0]), "r"((A)[1]), "r"((A)[2]), "r"((A)[3]), "r"(b0), "r"(b1))

__device__ __forceinline__ float sigf(float v) { return 1.f / (1.f + expf(-v)); }
__device__ __forceinline__ float4 ldcg4(const float *p) { return __ldcg((const float4 *)p); }
__device__ __forceinline__ float4 ldg4(const float *p) { return __ldg((const float4 *)p); }
__device__ __forceinline__ float4 add4(float4 a, float4 b) {
    return make_float4(a.x + b.x, a.y + b.y, a.z + b.z, a.w + b.w);
}
__device__ __forceinline__ void split_bf16(float v, __nv_bfloat16 &hi, __nv_bfloat16 &lo) {
    hi = __float2bfloat16(v);
    lo = __float2bfloat16(v - __bfloat162float(hi));
}

// ---------------- grid barrier: arrive-counter + release-flag ----------------
// Arrivals: proven single atomicAdd counter (no poll traffic on its line).
// Pollers spin on a SEPARATE flag written once per round by the last arriver.
// Release/acquire: each block fences before its add; the flag writer's add
// observed all adds (atomic total order); readers fence after seeing flag.
__device__ __forceinline__ void gsync(unsigned &round, int nblk) {
    __syncthreads();
    round += 1;
    if (threadIdx.x == 0) {
        __threadfence();
        unsigned prev = atomicAdd(&g_arrive, 1u);
        if (prev == round * (unsigned)nblk - 1u) {
            g_flag = round;          // volatile store (release of the round)
            __threadfence();
        }
        while (g_flag < round) { }
        __threadfence();
    }
    __syncthreads();
}

// ---------------- stage a 64x64 bf16 hi/lo tile pair via cp.async ----------
// swizzled 128B rows: byte = r*128 + ((c ^ (r&7)) << 4)
__device__ __forceinline__ void stage_tile64(unsigned dsthi, unsigned dstlo,
    const __nv_bfloat16 *__restrict__ hi, const __nv_bfloat16 *__restrict__ lo, int ld)
{
    const int t = threadIdx.x;
#pragma unroll
    for (int it = 0; it < 2; it++) {
        int idx = t + it * 256;
        int r = idx >> 3, c = idx & 7;
        unsigned off = (unsigned)(r * 128) + (unsigned)((c ^ (r & 7)) << 4);
        const int s = r * ld + c * 8;
        cpa16(dsthi + off, hi + s);
        cpa16(dstlo + off, lo + s);
    }
}

// ---------------- HMMA on one K=64 chunk ----------------
__device__ __forceinline__ void hmma_chunk(unsigned abuf, unsigned wbuf,
                                           int wm, int wn, int lane, float acc[2][2][4])
{
    const int lr = lane & 15;
    const int lh = lane >> 4;
#pragma unroll
    for (int ks = 0; ks < 4; ks++) {
        unsigned ah[2][4], al[2][4], bh[4], bl[4];
#pragma unroll
        for (int mt = 0; mt < 2; mt++) {
            int r = wm * 32 + mt * 16 + lr;
            unsigned ad = abuf + r * 128 + ((unsigned)((ks * 2 + lh) ^ (r & 7)) << 4);
            LDSM4(ah[mt], ad);
            LDSM4(al[mt], ad + 8192);
        }
        {
            int r = wn * 16 + lr;
            unsigned bd = wbuf + r * 128 + ((unsigned)((ks * 2 + lh) ^ (r & 7)) << 4);
            LDSM4(bh, bd);
            LDSM4(bl, bd + 8192);
        }
#pragma unroll
        for (int mt = 0; mt < 2; mt++) {
#pragma unroll
            for (int nt = 0; nt < 2; nt++) {
                unsigned h0 = nt ? bh[1] : bh[0], h1 = nt ? bh[3] : bh[2];
                unsigned l0 = nt ? bl[1] : bl[0], l1 = nt ? bl[3] : bl[2];
                MMA(acc[mt][nt], ah[mt], h0, h1);   // hi*hi
                MMA(acc[mt][nt], ah[mt], l0, l1);   // hi*lo
                MMA(acc[mt][nt], al[mt], h0, h1);   // lo*hi
            }
        }
    }
}

__device__ __forceinline__ void epilogue(float acc[2][2][4], float *__restrict__ Out,
                                         int m0, int n0, int w, int lane)
{
    const int wm = w & 1, wn = w >> 1;
    const int r0 = m0 + wm * 32 + (lane >> 2);
    const int cb = n0 + wn * 16 + (lane & 3) * 2;
#pragma unroll
    for (int mt = 0; mt < 2; mt++)
#pragma unroll
        for (int nt = 0; nt < 2; nt++) {
            float *p = Out + (r0 + mt * 16) * G3 + cb + nt * 8;
            *(float2 *)p = make_float2(acc[mt][nt][0], acc[mt][nt][1]);
            *(float2 *)(p + 8 * G3) = make_float2(acc[mt][nt][2], acc[mt][nt][3]);
        }
}

// ---------------- 64x64x256 tile with PERSISTENT weights -------------------
__device__ void hmma_tile_p(
    const __nv_bfloat16 *__restrict__ Ahi, const __nv_bfloat16 *__restrict__ Alo,
    int m0, int k0, unsigned wbase, float *__restrict__ Out, int n0,
    unsigned sb)
{
    const int tid = threadIdx.x;
    const int lane = tid & 31;
    const int w = tid >> 5;
    const int wm = w & 1, wn = w >> 1;

    float acc[2][2][4];
#pragma unroll
    for (int a = 0; a < 2; a++)
#pragma unroll
        for (int b = 0; b < 2; b++)
#pragma unroll
            for (int c = 0; c < 4; c++) acc[a][b][c] = 0.f;

    const __nv_bfloat16 *a0 = Ahi + m0 * Sv + k0;
    const __nv_bfloat16 *a1 = Alo + m0 * Sv + k0;

    stage_tile64(sb + OFF_AB, sb + OFF_AB + 8192, a0, a1, Sv);
    cpa_commit();
#pragma unroll
    for (int ch = 0; ch < 4; ch++) {
        if (ch < 3) {
            unsigned nb = sb + OFF_AB + (unsigned)(((ch + 1) & 1) * 16384);
            stage_tile64(nb, nb + 8192, a0 + (ch + 1) * 64, a1 + (ch + 1) * 64, Sv);
            cpa_commit();
            cpa_wait<1>();
        } else {
            cpa_wait<0>();
        }
        __syncthreads();
        hmma_chunk(sb + OFF_AB + (unsigned)((ch & 1) * 16384),
                   wbase + (unsigned)(ch * 16384), wm, wn, lane, acc);
        __syncthreads();
    }
    epilogue(acc, Out, m0, n0, w, lane);
}

// ---------------- gi0d tile: K=128 (2 chunks), staged A and W --------------
__device__ void hmma_tile_gi0d(int m0, int n0, unsigned sb)
{
    const int tid = threadIdx.x;
    const int lane = tid & 31;
    const int w = tid >> 5;
    const int wm = w & 1, wn = w >> 1;

    float acc[2][2][4];
#pragma unroll
    for (int a = 0; a < 2; a++)
#pragma unroll
        for (int b = 0; b < 2; b++)
#pragma unroll
            for (int c = 0; c < 4; c++) acc[a][b][c] = 0.f;

#pragma unroll
    for (int ch = 0; ch < 2; ch++) {
        stage_tile64(sb + OFF_AB, sb + OFF_AB + 8192,
                     g_fhi + m0 * 128 + ch * 64, g_flo + m0 * 128 + ch * 64, 128);
        stage_tile64(sb + OFF_AB + 16384, sb + OFF_AB + 16384 + 8192,
                     g_w0hi + n0 * 128 + ch * 64, g_w0lo + n0 * 128 + ch * 64, 128);
        cpa_commit();
        cpa_wait<0>();
        __syncthreads();
        hmma_chunk(sb + OFF_AB, sb + OFF_AB + 16384, wm, wn, lane, acc);
        __syncthreads();
    }
    epilogue(acc, g_gi0d, m0, n0, w, lane);
}

// ---------------- packed fp32x2 (pre_kernel GEMM) ----------------
__device__ __forceinline__ unsigned long long pack2(float a, float b) {
    unsigned long long r;
    asm("mov.b64 %0, {%1, %2};" : "=l"(r) : "f"(a), "f"(b));
    return r;
}
__device__ __forceinline__ unsigned long long ffma2(
    unsigned long long a, unsigned long long b, unsigned long long c) {
    unsigned long long d;
    asm("fma.rn.f32x2 %0, %1, %2, %3;" : "=l"(d) : "l"(a), "l"(b), "l"(c));
    return d;
}
union F2U { unsigned long long u; float2 f; };

// ---------------- kernel 1: init + encoder gi0 + weight conversions --------
__global__ void __launch_bounds__(256) pre_kernel(
    const float *__restrict__ x,
    const float *__restrict__ Wih0,
    const float *__restrict__ Whh0,
    const float *__restrict__ Whh1,
    const float *__restrict__ Wih1)
{
    __shared__ __align__(16) float shA[32 * 68];
    __shared__ __align__(16) float shW[32 * 68];
    const int tid = threadIdx.x;
    const int bx = blockIdx.x;

    if (bx < 64) {
        for (int i = bx * 256 + tid; i < Bv * Sv; i += 64 * 256) {
            g_h0[i] = 0.f; g_h1[i] = 0.f;
            __nv_bfloat16 z = __float2bfloat16(0.f);
            g_h0hi[i] = z; g_h0lo[i] = z; g_h1hi[i] = z; g_h1lo[i] = z;
        }
    }
    if (bx == 64) {
        for (int i = tid; i < Bv * 128; i += 256) {
            int b = i >> 7, c = i & 127;
            float v = (c < Cv) ? x[b * Tv * Cv + (Tv - 1) * Cv + c] : 0.f;
            __nv_bfloat16 hi, lo;
            split_bf16(v, hi, lo);
            g_fhi[i] = hi; g_flo[i] = lo;
            if (c < Cv) g_frame[b * Cv + c] = v;
        }
        if (tid == 0) { g_arrive = 0u; g_flag = 0u; }
    }
    {
        const int NW = G3 * Sv;
        const int TOT = 3 * NW + G3 * 128;
        const int stride = gridDim.x * 256;
        for (int i = bx * 256 + tid; i < TOT; i += stride) {
            __nv_bfloat16 hi, lo;
            if (i < NW) {
                split_bf16(__ldg(&Whh0[i]), hi, lo);
                g_whh0hi[i] = hi; g_whh0lo[i] = lo;
            } else if (i < 2 * NW) {
                int j = i - NW;
                split_bf16(__ldg(&Whh1[j]), hi, lo);
                g_whh1hi[j] = hi; g_whh1lo[j] = lo;
            } else if (i < 3 * NW) {
                int j = i - 2 * NW;
                split_bf16(__ldg(&Wih1[j]), hi, lo);
                g_wih1hi[j] = hi; g_wih1lo[j] = lo;
            } else {
                int j = i - 3 * NW;
                int n = j >> 7, k = j & 127;
                float v = (k < Cv) ? __ldg(&Wih0[n * Cv + k]) : 0.f;
                split_bf16(v, hi, lo);
                g_w0hi[j] = hi; g_w0lo[j] = lo;
            }
        }
    }

    // encoder gi0 tile (fp32 full precision)
    const int rt = bx / 24;
    const int nt = bx % 24;
    const int r0 = rt * 64, n0 = nt * 64;
    const int tx = tid & 15, ty = tid >> 4;
    const int lr = tid >> 5, lc = tid & 31;

    unsigned long long acc2[4][2];
#pragma unroll
    for (int i = 0; i < 4; i++) { acc2[i][0] = 0ull; acc2[i][1] = 0ull; }

    for (int kc = 0; kc < Cv; kc += 32) {
        __syncthreads();
#pragma unroll
        for (int it = 0; it < 8; it++) {
            int r = lr + it * 8;
            int kk = kc + lc;
            float av = 0.f, wv = 0.f;
            if (kk < Cv) {
                int rr = r0 + r;
                int t = rr >> 7, b = rr & 127;
                av = __ldg(&x[b * (Tv * Cv) + t * Cv + kk]);
                wv = __ldg(&Wih0[(n0 + r) * Cv + kk]);
            }
            shA[lc * 68 + r] = av;
            shW[lc * 68 + r] = wv;
        }
        __syncthreads();
#pragma unroll
        for (int k = 0; k < 32; ++k) {
            const float4 avv = *(const float4 *)(shA + k * 68 + (ty << 2));
            const ulonglong2 bp = *(const ulonglong2 *)(shW + k * 68 + (tx << 2));
            const unsigned long long q0 = pack2(avv.x, avv.x);
            const unsigned long long q1 = pack2(avv.y, avv.y);
            const unsigned long long q2 = pack2(avv.z, avv.z);
            const unsigned long long q3 = pack2(avv.w, avv.w);
            acc2[0][0] = ffma2(q0, bp.x, acc2[0][0]);
            acc2[0][1] = ffma2(q0, bp.y, acc2[0][1]);
            acc2[1][0] = ffma2(q1, bp.x, acc2[1][0]);
            acc2[1][1] = ffma2(q1, bp.y, acc2[1][1]);
            acc2[2][0] = ffma2(q2, bp.x, acc2[2][0]);
            acc2[2][1] = ffma2(q2, bp.y, acc2[2][1]);
            acc2[3][0] = ffma2(q3, bp.x, acc2[3][0]);
            acc2[3][1] = ffma2(q3, bp.y, acc2[3][1]);
        }
    }
#pragma unroll
    for (int i = 0; i < 4; i++) {
        int rr = r0 + (ty << 2) + i;
        int t = rr >> 7, b = rr & 127;
        F2U u0, u1;
        u0.u = acc2[i][0]; u1.u = acc2[i][1];
        *(float4 *)(&g_gi0[t * BG3 + b * G3 + n0 + (tx << 2)]) =
            make_float4(u0.f.x, u0.f.y, u1.f.x, u1.f.y);
    }
}

// ---------------- kernel 2: persistent RNN, persistent weights --------------
__global__ void __launch_bounds__(256, 1) rnn_kernel(
    const float *__restrict__ bih0, const float *__restrict__ bhh0,
    const float *__restrict__ bih1, const float *__restrict__ bhh1,
    const float *__restrict__ Wt, const float *__restrict__ bt,
    const float *__restrict__ Ws, const float *__restrict__ bs,
    float *__restrict__ out, int nblk)
{
    extern __shared__ char dynraw[];
    char *dyn = (char *)(((unsigned long long)dynraw + 1023) & ~1023ull);
    const unsigned sb = smem_u32(dyn);

    const int bid = blockIdx.x;
    const int tid = threadIdx.x;
    const int nth = nblk * 256;
    const int gtid = bid * 256 + tid;
    unsigned round = 0;

    // ---- per-block fixed tasks ----
    int a_m0 = 0, a_n0 = 0, a_k0 = 0;
    int b_m0 = 0, b_n0 = 0, b_k0 = 0;
    const __nv_bfloat16 *waHi = 0, *waLo = 0, *wbHi = 0, *wbLo = 0;
    const __nv_bfloat16 *aAhi = 0, *aAlo = 0, *bAhi = 0, *bAlo = 0;
    float *aOut = 0, *bOut = 0;
    const bool has_task = (bid < 144);
    if (bid < 96) {
        int kh = bid / 48, sub = bid % 48;
        a_m0 = (sub / 24) * 64; a_n0 = (sub % 24) * 64; a_k0 = kh * 256;
        waHi = g_whh0hi; waLo = g_whh0lo; aAhi = g_h0hi; aAlo = g_h0lo;
        aOut = g_p_gh0[kh];
        b_m0 = a_m0; b_n0 = a_n0; b_k0 = a_k0;
        wbHi = g_wih1hi; wbLo = g_wih1lo; bAhi = g_h0hi; bAlo = g_h0lo;
        bOut = g_p_gi1[kh];
    } else if (bid < 144) {
        int sub = bid - 96;
        a_m0 = (sub / 24) * 64; a_n0 = (sub % 24) * 64; a_k0 = 0;
        waHi = g_whh1hi; waLo = g_whh1lo; aAhi = g_h1hi; aAlo = g_h1lo;
        aOut = g_p_gh1[0];
        b_m0 = a_m0; b_n0 = a_n0; b_k0 = 256;
        wbHi = g_whh1hi; wbLo = g_whh1lo; bAhi = g_h1hi; bAlo = g_h1lo;
        bOut = g_p_gh1[1];
    }
    const int d_m0 = (bid >= 96 && bid < 144) ? (((bid - 96) / 24) * 64) : 0;
    const int d_n0 = (bid >= 96 && bid < 144) ? (((bid - 96) % 24) * 64) : 0;

    // ---- stage persistent weights (once) ----
    if (has_task) {
#pragma unroll
        for (int c = 0; c < 4; c++) {
            stage_tile64(sb + OFF_WA + c * 16384, sb + OFF_WA + c * 16384 + 8192,
                         waHi + a_n0 * Sv + a_k0 + c * 64,
                         waLo + a_n0 * Sv + a_k0 + c * 64, Sv);
            stage_tile64(sb + OFF_WB + c * 16384, sb + OFF_WB + c * 16384 + 8192,
                         wbHi + b_n0 * Sv + b_k0 + c * 64,
                         wbLo + b_n0 * Sv + b_k0 + c * 64, Sv);
        }
        cpa_commit();
        cpa_wait<0>();
    }
    __syncthreads();

    for (int step = 0; step < NSTEP; step++) {
        const bool dec = (step >= TENC);
        const int d = step - TENC;

        // ======== Phase A: gh0 + gh1-kh0 (persistent W) + [dec] gi0d
        if (has_task) {
            hmma_tile_p(aAhi, aAlo, a_m0, a_k0, sb + OFF_WA, aOut, a_n0, sb);
            if (dec && bid >= 96)
                hmma_tile_gi0d(d_m0, d_n0, sb);
        }
        gsync(round, nblk);

        // ======== gate0: h0 update
        {
            const float *GI = dec ? g_gi0d : (g_gi0 + step * BG3);
            for (int g = gtid; g < (Bv * Sv) / 4; g += nth) {
                int v = g << 2;
                int b = v >> 9, s = v & 511;
                const int rb = b * G3 + s;

                float4 ir = add4(ldcg4(GI + rb), ldg4(bih0 + s));
                float4 iz = add4(ldcg4(GI + rb + 512), ldg4(bih0 + 512 + s));
                float4 in_ = add4(ldcg4(GI + rb + 1024), ldg4(bih0 + 1024 + s));
                float4 hr = add4(add4(ldcg4(g_p_gh0[0] + rb), ldcg4(g_p_gh0[1] + rb)),
                                 ldg4(bhh0 + s));
                float4 hz = add4(add4(ldcg4(g_p_gh0[0] + rb + 512), ldcg4(g_p_gh0[1] + rb + 512)),
                                 ldg4(bhh0 + 512 + s));
                float4 hn = add4(add4(ldcg4(g_p_gh0[0] + rb + 1024), ldcg4(g_p_gh0[1] + rb + 1024)),
                                 ldg4(bhh0 + 1024 + s));
                float4 hold = ldcg4(g_h0 + v);

                float irv[4] = {ir.x, ir.y, ir.z, ir.w};
                float izv[4] = {iz.x, iz.y, iz.z, iz.w};
                float inv[4] = {in_.x, in_.y, in_.z, in_.w};
                float hrv[4] = {hr.x, hr.y, hr.z, hr.w};
                float hzv[4] = {hz.x, hz.y, hz.z, hz.w};
                float hnv[4] = {hn.x, hn.y, hn.z, hn.w};
                float hov[4] = {hold.x, hold.y, hold.z, hold.w};
                float res[4];
                __nv_bfloat16 rhi[4], rlo[4];
#pragma unroll
                for (int q = 0; q < 4; q++) {
                    float r = sigf(irv[q] + hrv[q]);
                    float z = sigf(izv[q] + hzv[q]);
                    float n = tanhf(inv[q] + r * hnv[q]);
                    res[q] = (1.f - z) * n + z * hov[q];
                    split_bf16(res[q], rhi[q], rlo[q]);
                }
                *(float4 *)(g_h0 + v) = make_float4(res[0], res[1], res[2], res[3]);
                __nv_bfloat162 *ph = (__nv_bfloat162 *)(g_h0hi + v);
                __nv_bfloat162 *pl = (__nv_bfloat162 *)(g_h0lo + v);
                ph[0] = __nv_bfloat162(rhi[0], rhi[1]);
                ph[1] = __nv_bfloat162(rhi[2], rhi[3]);
                pl[0] = __nv_bfloat162(rlo[0], rlo[1]);
                pl[1] = __nv_bfloat162(rlo[2], rlo[3]);
            }
        }
        gsync(round, nblk);

        // ======== Phase B: gi1 + gh1-kh1 (persistent W)
        if (has_task)
            hmma_tile_p(bAhi, bAlo, b_m0, b_k0, sb + OFF_WB, bOut, b_n0, sb);
        gsync(round, nblk);

        // ======== gate1 (+ global hist, window) + decoder projection
        if (bid < Bv) {
            const int b = bid;
            float *shT = (float *)(dyn + OFF_GATE);
            float *shR = shT + 512;
            float *shWt = shR + 160;
            if (dec && tid < 32) shWt[tid] = __ldg(&Wt[tid]);
            __syncthreads();
            const float bt0 = __ldg(&bt[0]);

            for (int s = tid; s < Sv; s += 256) {
                const int rb = b * G3 + s;
                float ir = __ldg(&bih1[s]) + __ldcg(&g_p_gi1[0][rb]) + __ldcg(&g_p_gi1[1][rb]);
                float iz = __ldg(&bih1[512 + s]) + __ldcg(&g_p_gi1[0][rb + 512]) + __ldcg(&g_p_gi1[1][rb + 512]);
                float in_ = __ldg(&bih1[1024 + s]) + __ldcg(&g_p_gi1[0][rb + 1024]) + __ldcg(&g_p_gi1[1][rb + 1024]);
                float hr = __ldg(&bhh1[s]) + __ldcg(&g_p_gh1[0][rb]) + __ldcg(&g_p_gh1[1][rb]);
                float hz = __ldg(&bhh1[512 + s]) + __ldcg(&g_p_gh1[0][rb + 512]) + __ldcg(&g_p_gh1[1][rb + 512]);
                float hn = __ldg(&bhh1[1024 + s]) + __ldcg(&g_p_gh1[0][rb + 1024]) + __ldcg(&g_p_gh1[1][rb + 1024]);
                float r = sigf(ir + hr);
                float z = sigf(iz + hz);
                float n = tanhf(in_ + r * hn);
                float h1n = (1.f - z) * n + z * g_h1[b * Sv + s];
                g_h1[b * Sv + s] = h1n;
                g_hist[step * (Bv * Sv) + b * Sv + s] = h1n;
                __nv_bfloat16 hh, hl;
                split_bf16(h1n, hh, hl);
                g_h1hi[b * Sv + s] = hh;
                g_h1lo[b * Sv + s] = hl;
                if (dec) {
                    float acc = bt0;
                    const float *hp = g_hist + b * Sv + s;
#pragma unroll
                    for (int w = 0; w < Wwin - 1; w++)
                        acc += shWt[w] * hp[(32 + d + w) * (Bv * Sv)];
                    acc += shWt[Wwin - 1] * h1n;
                    shT[s] = acc;
                }
            }
            if (dec) {
                __syncthreads();
                if (tid < 2 * Cv) {
                    int c = tid >> 1, h = tid & 1;
                    const float *wr = Ws + c * Sv + h * 256;
                    const float *tr = shT + h * 256;
                    float p0 = 0.f, p1 = 0.f, p2 = 0.f, p3 = 0.f;
#pragma unroll 4
                    for (int s = 0; s < 256; s += 4) {
                        p0 += tr[s + 0] * __ldg(&wr[s + 0]);
                        p1 += tr[s + 1] * __ldg(&wr[s + 1]);
                        p2 += tr[s + 2] * __ldg(&wr[s + 2]);
                        p3 += tr[s + 3] * __ldg(&wr[s + 3]);
                    }
                    shR[tid] = (p0 + p1) + (p2 + p3);
                }
                __syncthreads();
                if (tid < Cv) {
                    float ov = shR[2 * tid] + shR[2 * tid + 1] + __ldg(&bs[tid]);
                    float nf = ov + g_frame[b * Cv + tid];
                    out[b * (Tv * Cv) + d * Cv + tid] = nf;
                    g_frame[b * Cv + tid] = nf;
                    __nv_bfloat16 fh, fl;
                    split_bf16(nf, fh, fl);
                    g_fhi[b * 128 + tid] = fh;
                    g_flo[b * 128 + tid] = fl;
                }
            }
        }
        gsync(round, nblk);
    }
}

// ---------------- launch ----------------
extern "C" void kernel_launch(void *const *d_in, const int *in_sizes, int n_in,
                              void *d_out, int out_size)
{
    const float *x    = (const float *)d_in[0];
    const float *Wih0 = (const float *)d_in[1];
    const float *Whh0 = (const float *)d_in[2];
    const float *bih0 = (const float *)d_in[3];
    const float *bhh0 = (const float *)d_in[4];
    const float *Wih1 = (const float *)d_in[5];
    const float *Whh1 = (const float *)d_in[6];
    const float *bih1 = (const float *)d_in[7];
    const float *bhh1 = (const float *)d_in[8];
    const float *Wt   = (const float *)d_in[9];
    const float *bt   = (const float *)d_in[10];
    const float *Ws   = (const float *)d_in[11];
    const float *bs   = (const float *)d_in[12];
    float *out = (float *)d_out;

    int dev = 0;
    cudaGetDevice(&dev);
    int nsm = 0;
    cudaDeviceGetAttribute(&nsm, cudaDevAttrMultiProcessorCount, dev);
    if (nsm < 144) nsm = 148;

    cudaFuncSetAttribute(rnn_kernel, cudaFuncAttributeMaxDynamicSharedMemorySize, SMEM_DYN);

    pre_kernel<<<126 * 24, 256>>>(x, Wih0, Whh0, Whh1, Wih1);
    rnn_kernel<<<nsm, 256, SMEM_DYN>>>(bih0, bhh0, bih1, bhh1,
                                       Wt, bt, Ws, bs, out, nsm);
}

// round 15
// speedup vs baseline: 1.7576x; 1.0415x over previous
#include <cuda_runtime.h>
#include <cuda_bf16.h>
#include <math.h>

#define Bv 128
#define Tv 64
#define Cv 66
#define Sv 512
#define Wwin 32
#define G3 1536
#define TENC 63
#define NSTEP 127
#define BG3 (Bv * G3)
#define NTH 512

// dynamic smem layout (relative to 1024-aligned base)
#define OFF_WA 0              // phase-A weights: 4 chunks x {hi 8K, lo 8K} = 64K
#define OFF_WB 65536          // phase-B weights: 64K
#define OFF_AB 131072         // A-operand double buffer: 2 x 16K = 32K
#define OFF_GATE 163840       // gate1 scratch
#define SMEM_DYN (OFF_GATE + 2816 + 1024)

// ---------------- device scratch ----------------
__device__ float g_h0[Bv * Sv];
__device__ float g_h1[Bv * Sv];
__device__ float g_hist[NSTEP * Bv * Sv];
__device__ float g_gi0[TENC * BG3];
__device__ float g_gi0d[BG3];
__device__ float g_p_gh0[2][BG3];
__device__ float g_p_gh1[2][BG3];
__device__ float g_p_gi1[2][BG3];
__device__ float g_frame[Bv * Cv];
__device__ unsigned int g_arrive;

__device__ __nv_bfloat16 g_h0hi[Bv * Sv], g_h0lo[Bv * Sv];
__device__ __nv_bfloat16 g_h1hi[Bv * Sv], g_h1lo[Bv * Sv];
__device__ __nv_bfloat16 g_fhi[Bv * 128], g_flo[Bv * 128];
__device__ __nv_bfloat16 g_whh0hi[G3 * Sv], g_whh0lo[G3 * Sv];
__device__ __nv_bfloat16 g_whh1hi[G3 * Sv], g_whh1lo[G3 * Sv];
__device__ __nv_bfloat16 g_wih1hi[G3 * Sv], g_wih1lo[G3 * Sv];
__device__ __nv_bfloat16 g_w0hi[G3 * 128], g_w0lo[G3 * 128];

// ---------------- helpers ----------------
__device__ __forceinline__ unsigned smem_u32(const void *p) {
    unsigned a;
    asm("{ .reg .u64 t; cvta.to.shared.u64 t, %1; cvt.u32.u64 %0, t; }" : "=r"(a) : "l"(p));
    return a;
}
__device__ __forceinline__ void cpa16(unsigned dst, const void *src) {
    asm volatile("cp.async.cg.shared.global [%0], [%1], 16;" :: "r"(dst), "l"(src));
}
__device__ __forceinline__ void cpa_commit() {
    asm volatile("cp.async.commit_group;" ::: "memory");
}
template <int N> __device__ __forceinline__ void cpa_wait() {
    asm volatile("cp.async.wait_group %0;" :: "n"(N) : "memory");
}
#define LDSM4(R, addr) \
    asm volatile("ldmatrix.sync.aligned.m8n8.x4.shared.b16 {%0,%1,%2,%3}, [%4];" \
        : "=r"((R)[0]), "=r"((R)[1]), "=r"((R)[2]), "=r"((R)[3]) : "r"(addr))
#define MMA(D, A, b0, b1) \
    asm volatile("mma.sync.aligned.m16n8k16.row.col.f32.bf16.bf16.f32 " \
        "{%0,%1,%2,%3}, {%4,%5,%6,%7}, {%8,%9}, {%0,%1,%2,%3};" \
        : "+f"((D)[0]), "+f"((D)[1]), "+f"((D)[2]), "+f"((D)[3]) \
        : "r"((A)[0]), "r"((A)[1]), "r"((A)[2]), "r"((A)[3]), "r"(b0), "r"(b1))

__device__ __forceinline__ float sigf(float v) { return 1.f / (1.f + expf(-v)); }
__device__ __forceinline__ float4 ldcg4(const float *p) { return __ldcg((const float4 *)p); }
__device__ __forceinline__ float4 ldg4(const float *p) { return __ldg((const float4 *)p); }
__device__ __forceinline__ float4 add4(float4 a, float4 b) {
    return make_float4(a.x + b.x, a.y + b.y, a.z + b.z, a.w + b.w);
}
__device__ __forceinline__ void split_bf16(float v, __nv_bfloat16 &hi, __nv_bfloat16 &lo) {
    hi = __float2bfloat16(v);
    lo = __float2bfloat16(v - __bfloat162float(hi));
}

// ---------------- grid barrier (PROVEN single-counter) ----------------
__device__ __forceinline__ void gsync(unsigned &tgt, int nblk) {
    __syncthreads();
    tgt += (unsigned)nblk;
    if (threadIdx.x == 0) {
        __threadfence();
        atomicAdd(&g_arrive, 1u);
        while (*(volatile unsigned *)&g_arrive < tgt) { }
        __threadfence();
    }
    __syncthreads();
}

// ---------------- stage a 64x64 bf16 hi/lo tile pair (512 threads) ----------
// swizzled 128B rows: byte = r*128 + ((c ^ (r&7)) << 4)
__device__ __forceinline__ void stage_tile64(unsigned dsthi, unsigned dstlo,
    const __nv_bfloat16 *__restrict__ hi, const __nv_bfloat16 *__restrict__ lo, int ld)
{
    const int t = threadIdx.x;          // 0..511 = 64 rows x 8 col-chunks
    int r = t >> 3, c = t & 7;
    unsigned off = (unsigned)(r * 128) + (unsigned)((c ^ (r & 7)) << 4);
    const int s = r * ld + c * 8;
    cpa16(dsthi + off, hi + s);
    cpa16(dstlo + off, lo + s);
}

// ---------------- HMMA on one K=64 chunk: 16 warps, warp tile m16 x n16 -----
__device__ __forceinline__ void hmma_chunk(unsigned abuf, unsigned wbuf,
                                           int wm, int wn, int lane, float acc[2][4])
{
    const int lr = lane & 15;
    const int lh = lane >> 4;
#pragma unroll
    for (int ks = 0; ks < 4; ks++) {
        unsigned ah[4], al[4], bh[4], bl[4];
        {
            int r = wm * 16 + lr;
            unsigned ad = abuf + r * 128 + ((unsigned)((ks * 2 + lh) ^ (r & 7)) << 4);
            LDSM4(ah, ad);
            LDSM4(al, ad + 8192);
        }
        {
            int r = wn * 16 + lr;
            unsigned bd = wbuf + r * 128 + ((unsigned)((ks * 2 + lh) ^ (r & 7)) << 4);
            LDSM4(bh, bd);
            LDSM4(bl, bd + 8192);
        }
#pragma unroll
        for (int nt = 0; nt < 2; nt++) {
            unsigned h0 = nt ? bh[1] : bh[0], h1 = nt ? bh[3] : bh[2];
            unsigned l0 = nt ? bl[1] : bl[0], l1 = nt ? bl[3] : bl[2];
            MMA(acc[nt], ah, h0, h1);   // hi*hi
            MMA(acc[nt], ah, l0, l1);   // hi*lo
            MMA(acc[nt], al, h0, h1);   // lo*hi
        }
    }
}

__device__ __forceinline__ void epilogue(float acc[2][4], float *__restrict__ Out,
                                         int m0, int n0, int wm, int wn, int lane)
{
    const int r0 = m0 + wm * 16 + (lane >> 2);
    const int cb = n0 + wn * 16 + (lane & 3) * 2;
#pragma unroll
    for (int nt = 0; nt < 2; nt++) {
        float *p = Out + r0 * G3 + cb + nt * 8;
        *(float2 *)p = make_float2(acc[nt][0], acc[nt][1]);
        *(float2 *)(p + 8 * G3) = make_float2(acc[nt][2], acc[nt][3]);
    }
}

// ---------------- 64x64x256 tile with PERSISTENT weights (16 warps) --------
__device__ void hmma_tile_p(
    const __nv_bfloat16 *__restrict__ Ahi, const __nv_bfloat16 *__restrict__ Alo,
    int m0, int k0, unsigned wbase, float *__restrict__ Out, int n0,
    unsigned sb)
{
    const int tid = threadIdx.x;
    const int lane = tid & 31;
    const int w = tid >> 5;           // 0..15
    const int wm = w & 3, wn = w >> 2;

    float acc[2][4];
#pragma unroll
    for (int b = 0; b < 2; b++)
#pragma unroll
        for (int c = 0; c < 4; c++) acc[b][c] = 0.f;

    const __nv_bfloat16 *a0 = Ahi + m0 * Sv + k0;
    const __nv_bfloat16 *a1 = Alo + m0 * Sv + k0;

    stage_tile64(sb + OFF_AB, sb + OFF_AB + 8192, a0, a1, Sv);
    cpa_commit();
#pragma unroll
    for (int ch = 0; ch < 4; ch++) {
        if (ch < 3) {
            unsigned nb = sb + OFF_AB + (unsigned)(((ch + 1) & 1) * 16384);
            stage_tile64(nb, nb + 8192, a0 + (ch + 1) * 64, a1 + (ch + 1) * 64, Sv);
            cpa_commit();
            cpa_wait<1>();
        } else {
            cpa_wait<0>();
        }
        __syncthreads();
        hmma_chunk(sb + OFF_AB + (unsigned)((ch & 1) * 16384),
                   wbase + (unsigned)(ch * 16384), wm, wn, lane, acc);
        __syncthreads();
    }
    epilogue(acc, Out, m0, n0, wm, wn, lane);
}

// ---------------- gi0d tile: K=128 (2 chunks), staged A and W --------------
__device__ void hmma_tile_gi0d(int m0, int n0, unsigned sb)
{
    const int tid = threadIdx.x;
    const int lane = tid & 31;
    const int w = tid >> 5;
    const int wm = w & 3, wn = w >> 2;

    float acc[2][4];
#pragma unroll
    for (int b = 0; b < 2; b++)
#pragma unroll
        for (int c = 0; c < 4; c++) acc[b][c] = 0.f;

#pragma unroll
    for (int ch = 0; ch < 2; ch++) {
        stage_tile64(sb + OFF_AB, sb + OFF_AB + 8192,
                     g_fhi + m0 * 128 + ch * 64, g_flo + m0 * 128 + ch * 64, 128);
        stage_tile64(sb + OFF_AB + 16384, sb + OFF_AB + 16384 + 8192,
                     g_w0hi + n0 * 128 + ch * 64, g_w0lo + n0 * 128 + ch * 64, 128);
        cpa_commit();
        cpa_wait<0>();
        __syncthreads();
        hmma_chunk(sb + OFF_AB, sb + OFF_AB + 16384, wm, wn, lane, acc);
        __syncthreads();
    }
    epilogue(acc, g_gi0d, m0, n0, wm, wn, lane);
}

// ---------------- packed fp32x2 (pre_kernel GEMM) ----------------
__device__ __forceinline__ unsigned long long pack2(float a, float b) {
    unsigned long long r;
    asm("mov.b64 %0, {%1, %2};" : "=l"(r) : "f"(a), "f"(b));
    return r;
}
__device__ __forceinline__ unsigned long long ffma2(
    unsigned long long a, unsigned long long b, unsigned long long c) {
    unsigned long long d;
    asm("fma.rn.f32x2 %0, %1, %2, %3;" : "=l"(d) : "l"(a), "l"(b), "l"(c));
    return d;
}
union F2U { unsigned long long u; float2 f; };

// ---------------- kernel 1: init + encoder gi0 + weight conversions --------
__global__ void __launch_bounds__(256) pre_kernel(
    const float *__restrict__ x,
    const float *__restrict__ Wih0,
    const float *__restrict__ Whh0,
    const float *__restrict__ Whh1,
    const float *__restrict__ Wih1)
{
    __shared__ __align__(16) float shA[32 * 68];
    __shared__ __align__(16) float shW[32 * 68];
    const int tid = threadIdx.x;
    const int bx = blockIdx.x;

    if (bx < 64) {
        for (int i = bx * 256 + tid; i < Bv * Sv; i += 64 * 256) {
            g_h0[i] = 0.f; g_h1[i] = 0.f;
            __nv_bfloat16 z = __float2bfloat16(0.f);
            g_h0hi[i] = z; g_h0lo[i] = z; g_h1hi[i] = z; g_h1lo[i] = z;
        }
    }
    if (bx == 64) {
        for (int i = tid; i < Bv * 128; i += 256) {
            int b = i >> 7, c = i & 127;
            float v = (c < Cv) ? x[b * Tv * Cv + (Tv - 1) * Cv + c] : 0.f;
            __nv_bfloat16 hi, lo;
            split_bf16(v, hi, lo);
            g_fhi[i] = hi; g_flo[i] = lo;
            if (c < Cv) g_frame[b * Cv + c] = v;
        }
        if (tid == 0) g_arrive = 0u;
    }
    {
        const int NW = G3 * Sv;
        const int TOT = 3 * NW + G3 * 128;
        const int stride = gridDim.x * 256;
        for (int i = bx * 256 + tid; i < TOT; i += stride) {
            __nv_bfloat16 hi, lo;
            if (i < NW) {
                split_bf16(__ldg(&Whh0[i]), hi, lo);
                g_whh0hi[i] = hi; g_whh0lo[i] = lo;
            } else if (i < 2 * NW) {
                int j = i - NW;
                split_bf16(__ldg(&Whh1[j]), hi, lo);
                g_whh1hi[j] = hi; g_whh1lo[j] = lo;
            } else if (i < 3 * NW) {
                int j = i - 2 * NW;
                split_bf16(__ldg(&Wih1[j]), hi, lo);
                g_wih1hi[j] = hi; g_wih1lo[j] = lo;
            } else {
                int j = i - 3 * NW;
                int n = j >> 7, k = j & 127;
                float v = (k < Cv) ? __ldg(&Wih0[n * Cv + k]) : 0.f;
                split_bf16(v, hi, lo);
                g_w0hi[j] = hi; g_w0lo[j] = lo;
            }
        }
    }

    // encoder gi0 tile (fp32 full precision)
    const int rt = bx / 24;
    const int nt = bx % 24;
    const int r0 = rt * 64, n0 = nt * 64;
    const int tx = tid & 15, ty = tid >> 4;
    const int lr = tid >> 5, lc = tid & 31;

    unsigned long long acc2[4][2];
#pragma unroll
    for (int i = 0; i < 4; i++) { acc2[i][0] = 0ull; acc2[i][1] = 0ull; }

    for (int kc = 0; kc < Cv; kc += 32) {
        __syncthreads();
#pragma unroll
        for (int it = 0; it < 8; it++) {
            int r = lr + it * 8;
            int kk = kc + lc;
            float av = 0.f, wv = 0.f;
            if (kk < Cv) {
                int rr = r0 + r;
                int t = rr >> 7, b = rr & 127;
                av = __ldg(&x[b * (Tv * Cv) + t * Cv + kk]);
                wv = __ldg(&Wih0[(n0 + r) * Cv + kk]);
            }
            shA[lc * 68 + r] = av;
            shW[lc * 68 + r] = wv;
        }
        __syncthreads();
#pragma unroll
        for (int k = 0; k < 32; ++k) {
            const float4 avv = *(const float4 *)(shA + k * 68 + (ty << 2));
            const ulonglong2 bp = *(const ulonglong2 *)(shW + k * 68 + (tx << 2));
            const unsigned long long q0 = pack2(avv.x, avv.x);
            const unsigned long long q1 = pack2(avv.y, avv.y);
            const unsigned long long q2 = pack2(avv.z, avv.z);
            const unsigned long long q3 = pack2(avv.w, avv.w);
            acc2[0][0] = ffma2(q0, bp.x, acc2[0][0]);
            acc2[0][1] = ffma2(q0, bp.y, acc2[0][1]);
            acc2[1][0] = ffma2(q1, bp.x, acc2[1][0]);
            acc2[1][1] = ffma2(q1, bp.y, acc2[1][1]);
            acc2[2][0] = ffma2(q2, bp.x, acc2[2][0]);
            acc2[2][1] = ffma2(q2, bp.y, acc2[2][1]);
            acc2[3][0] = ffma2(q3, bp.x, acc2[3][0]);
            acc2[3][1] = ffma2(q3, bp.y, acc2[3][1]);
        }
    }
#pragma unroll
    for (int i = 0; i < 4; i++) {
        int rr = r0 + (ty << 2) + i;
        int t = rr >> 7, b = rr & 127;
        F2U u0, u1;
        u0.u = acc2[i][0]; u1.u = acc2[i][1];
        *(float4 *)(&g_gi0[t * BG3 + b * G3 + n0 + (tx << 2)]) =
            make_float4(u0.f.x, u0.f.y, u1.f.x, u1.f.y);
    }
}

// ---------------- kernel 2: persistent RNN, 512 threads, persistent W ------
__global__ void __launch_bounds__(NTH, 1) rnn_kernel(
    const float *__restrict__ bih0, const float *__restrict__ bhh0,
    const float *__restrict__ bih1, const float *__restrict__ bhh1,
    const float *__restrict__ Wt, const float *__restrict__ bt,
    const float *__restrict__ Ws, const float *__restrict__ bs,
    float *__restrict__ out, int nblk)
{
    extern __shared__ char dynraw[];
    char *dyn = (char *)(((unsigned long long)dynraw + 1023) & ~1023ull);
    const unsigned sb = smem_u32(dyn);

    const int bid = blockIdx.x;
    const int tid = threadIdx.x;
    const int nth = nblk * NTH;
    const int gtid = bid * NTH + tid;
    unsigned tgt = 0;

    // ---- per-block fixed tasks (same map as R12) ----
    int a_m0 = 0, a_n0 = 0, a_k0 = 0;
    int b_m0 = 0, b_n0 = 0, b_k0 = 0;
    const __nv_bfloat16 *waHi = 0, *waLo = 0, *wbHi = 0, *wbLo = 0;
    const __nv_bfloat16 *aAhi = 0, *aAlo = 0, *bAhi = 0, *bAlo = 0;
    float *aOut = 0, *bOut = 0;
    const bool has_task = (bid < 144);
    if (bid < 96) {
        int kh = bid / 48, sub = bid % 48;
        a_m0 = (sub / 24) * 64; a_n0 = (sub % 24) * 64; a_k0 = kh * 256;
        waHi = g_whh0hi; waLo = g_whh0lo; aAhi = g_h0hi; aAlo = g_h0lo;
        aOut = g_p_gh0[kh];
        b_m0 = a_m0; b_n0 = a_n0; b_k0 = a_k0;
        wbHi = g_wih1hi; wbLo = g_wih1lo; bAhi = g_h0hi; bAlo = g_h0lo;
        bOut = g_p_gi1[kh];
    } else if (bid < 144) {
        int sub = bid - 96;
        a_m0 = (sub / 24) * 64; a_n0 = (sub % 24) * 64; a_k0 = 0;
        waHi = g_whh1hi; waLo = g_whh1lo; aAhi = g_h1hi; aAlo = g_h1lo;
        aOut = g_p_gh1[0];
        b_m0 = a_m0; b_n0 = a_n0; b_k0 = 256;
        wbHi = g_whh1hi; wbLo = g_whh1lo; bAhi = g_h1hi; bAlo = g_h1lo;
        bOut = g_p_gh1[1];
    }
    const int d_m0 = (bid >= 96 && bid < 144) ? (((bid - 96) / 24) * 64) : 0;
    const int d_n0 = (bid >= 96 && bid < 144) ? (((bid - 96) % 24) * 64) : 0;

    // ---- stage persistent weights (once) ----
    if (has_task) {
#pragma unroll
        for (int c = 0; c < 4; c++) {
            stage_tile64(sb + OFF_WA + c * 16384, sb + OFF_WA + c * 16384 + 8192,
                         waHi + a_n0 * Sv + a_k0 + c * 64,
                         waLo + a_n0 * Sv + a_k0 + c * 64, Sv);
            stage_tile64(sb + OFF_WB + c * 16384, sb + OFF_WB + c * 16384 + 8192,
                         wbHi + b_n0 * Sv + b_k0 + c * 64,
                         wbLo + b_n0 * Sv + b_k0 + c * 64, Sv);
        }
        cpa_commit();
        cpa_wait<0>();
    }
    __syncthreads();

    for (int step = 0; step < NSTEP; step++) {
        const bool dec = (step >= TENC);
        const int d = step - TENC;

        // ======== Phase A: gh0 + gh1-kh0 (persistent W) + [dec] gi0d
        if (has_task) {
            hmma_tile_p(aAhi, aAlo, a_m0, a_k0, sb + OFF_WA, aOut, a_n0, sb);
            if (dec && bid >= 96)
                hmma_tile_gi0d(d_m0, d_n0, sb);
        }
        gsync(tgt, nblk);

        // ======== gate0: h0 update
        {
            const float *GI = dec ? g_gi0d : (g_gi0 + step * BG3);
            for (int g = gtid; g < (Bv * Sv) / 4; g += nth) {
                int v = g << 2;
                int b = v >> 9, s = v & 511;
                const int rb = b * G3 + s;

                float4 ir = add4(ldcg4(GI + rb), ldg4(bih0 + s));
                float4 iz = add4(ldcg4(GI + rb + 512), ldg4(bih0 + 512 + s));
                float4 in_ = add4(ldcg4(GI + rb + 1024), ldg4(bih0 + 1024 + s));
                float4 hr = add4(add4(ldcg4(g_p_gh0[0] + rb), ldcg4(g_p_gh0[1] + rb)),
                                 ldg4(bhh0 + s));
                float4 hz = add4(add4(ldcg4(g_p_gh0[0] + rb + 512), ldcg4(g_p_gh0[1] + rb + 512)),
                                 ldg4(bhh0 + 512 + s));
                float4 hn = add4(add4(ldcg4(g_p_gh0[0] + rb + 1024), ldcg4(g_p_gh0[1] + rb + 1024)),
                                 ldg4(bhh0 + 1024 + s));
                float4 hold = ldcg4(g_h0 + v);

                float irv[4] = {ir.x, ir.y, ir.z, ir.w};
                float izv[4] = {iz.x, iz.y, iz.z, iz.w};
                float inv[4] = {in_.x, in_.y, in_.z, in_.w};
                float hrv[4] = {hr.x, hr.y, hr.z, hr.w};
                float hzv[4] = {hz.x, hz.y, hz.z, hz.w};
                float hnv[4] = {hn.x, hn.y, hn.z, hn.w};
                float hov[4] = {hold.x, hold.y, hold.z, hold.w};
                float res[4];
                __nv_bfloat16 rhi[4], rlo[4];
#pragma unroll
                for (int q = 0; q < 4; q++) {
                    float r = sigf(irv[q] + hrv[q]);
                    float z = sigf(izv[q] + hzv[q]);
                    float n = tanhf(inv[q] + r * hnv[q]);
                    res[q] = (1.f - z) * n + z * hov[q];
                    split_bf16(res[q], rhi[q], rlo[q]);
                }
                *(float4 *)(g_h0 + v) = make_float4(res[0], res[1], res[2], res[3]);
                __nv_bfloat162 *ph = (__nv_bfloat162 *)(g_h0hi + v);
                __nv_bfloat162 *pl = (__nv_bfloat162 *)(g_h0lo + v);
                ph[0] = __nv_bfloat162(rhi[0], rhi[1]);
                ph[1] = __nv_bfloat162(rhi[2], rhi[3]);
                pl[0] = __nv_bfloat162(rlo[0], rlo[1]);
                pl[1] = __nv_bfloat162(rlo[2], rlo[3]);
            }
        }
        gsync(tgt, nblk);

        // ======== Phase B: gi1 + gh1-kh1 (persistent W)
        if (has_task)
            hmma_tile_p(bAhi, bAlo, b_m0, b_k0, sb + OFF_WB, bOut, b_n0, sb);
        gsync(tgt, nblk);

        // ======== gate1 (+ global hist, window) + decoder projection
        if (bid < Bv) {
            const int b = bid;
            float *shT = (float *)(dyn + OFF_GATE);
            float *shR = shT + 512;
            float *shWt = shR + 160;
            if (dec && tid < 32) shWt[tid] = __ldg(&Wt[tid]);
            __syncthreads();
            const float bt0 = __ldg(&bt[0]);

            {
                const int s = tid;     // NTH == Sv: one element per thread
                const int rb = b * G3 + s;
                float ir = __ldg(&bih1[s]) + __ldcg(&g_p_gi1[0][rb]) + __ldcg(&g_p_gi1[1][rb]);
                float iz = __ldg(&bih1[512 + s]) + __ldcg(&g_p_gi1[0][rb + 512]) + __ldcg(&g_p_gi1[1][rb + 512]);
                float in_ = __ldg(&bih1[1024 + s]) + __ldcg(&g_p_gi1[0][rb + 1024]) + __ldcg(&g_p_gi1[1][rb + 1024]);
                float hr = __ldg(&bhh1[s]) + __ldcg(&g_p_gh1[0][rb]) + __ldcg(&g_p_gh1[1][rb]);
                float hz = __ldg(&bhh1[512 + s]) + __ldcg(&g_p_gh1[0][rb + 512]) + __ldcg(&g_p_gh1[1][rb + 512]);
                float hn = __ldg(&bhh1[1024 + s]) + __ldcg(&g_p_gh1[0][rb + 1024]) + __ldcg(&g_p_gh1[1][rb + 1024]);
                float r = sigf(ir + hr);
                float z = sigf(iz + hz);
                float n = tanhf(in_ + r * hn);
                float h1n = (1.f - z) * n + z * g_h1[b * Sv + s];
                g_h1[b * Sv + s] = h1n;
                g_hist[step * (Bv * Sv) + b * Sv + s] = h1n;
                __nv_bfloat16 hh, hl;
                split_bf16(h1n, hh, hl);
                g_h1hi[b * Sv + s] = hh;
                g_h1lo[b * Sv + s] = hl;
                if (dec) {
                    float acc = bt0;
                    const float *hp = g_hist + b * Sv + s;
#pragma unroll
                    for (int w = 0; w < Wwin - 1; w++)
                        acc += shWt[w] * hp[(32 + d + w) * (Bv * Sv)];
                    acc += shWt[Wwin - 1] * h1n;
                    shT[s] = acc;
                }
            }
            if (dec) {
                __syncthreads();
                if (tid < 2 * Cv) {
                    int c = tid >> 1, h = tid & 1;
                    const float *wr = Ws + c * Sv + h * 256;
                    const float *tr = shT + h * 256;
                    float p0 = 0.f, p1 = 0.f, p2 = 0.f, p3 = 0.f;
#pragma unroll 4
                    for (int s = 0; s < 256; s += 4) {
                        p0 += tr[s + 0] * __ldg(&wr[s + 0]);
                        p1 += tr[s + 1] * __ldg(&wr[s + 1]);
                        p2 += tr[s + 2] * __ldg(&wr[s + 2]);
                        p3 += tr[s + 3] * __ldg(&wr[s + 3]);
                    }
                    shR[tid] = (p0 + p1) + (p2 + p3);
                }
                __syncthreads();
                if (tid < Cv) {
                    float ov = shR[2 * tid] + shR[2 * tid + 1] + __ldg(&bs[tid]);
                    float nf = ov + g_frame[b * Cv + tid];
                    out[b * (Tv * Cv) + d * Cv + tid] = nf;
                    g_frame[b * Cv + tid] = nf;
                    __nv_bfloat16 fh, fl;
                    split_bf16(nf, fh, fl);
                    g_fhi[b * 128 + tid] = fh;
                    g_flo[b * 128 + tid] = fl;
                }
            }
        }
        gsync(tgt, nblk);
    }
}

// ---------------- launch ----------------
extern "C" void kernel_launch(void *const *d_in, const int *in_sizes, int n_in,
                              void *d_out, int out_size)
{
    const float *x    = (const float *)d_in[0];
    const float *Wih0 = (const float *)d_in[1];
    const float *Whh0 = (const float *)d_in[2];
    const float *bih0 = (const float *)d_in[3];
    const float *bhh0 = (const float *)d_in[4];
    const float *Wih1 = (const float *)d_in[5];
    const float *Whh1 = (const float *)d_in[6];
    const float *bih1 = (const float *)d_in[7];
    const float *bhh1 = (const float *)d_in[8];
    const float *Wt   = (const float *)d_in[9];
    const float *bt   = (const float *)d_in[10];
    const float *Ws   = (const float *)d_in[11];
    const float *bs   = (const float *)d_in[12];
    float *out = (float *)d_out;

    int dev = 0;
    cudaGetDevice(&dev);
    int nsm = 0;
    cudaDeviceGetAttribute(&nsm, cudaDevAttrMultiProcessorCount, dev);
    if (nsm < 144) nsm = 148;

    cudaFuncSetAttribute(rnn_kernel, cudaFuncAttributeMaxDynamicSharedMemorySize, SMEM_DYN);

    pre_kernel<<<126 * 24, 256>>>(x, Wih0, Whh0, Whh1, Wih1);
    rnn_kernel<<<nsm, NTH, SMEM_DYN>>>(bih0, bhh0, bih1, bhh1,
                                       Wt, bt, Ws, bs, out, nsm);
}

// round 16
// speedup vs baseline: 1.7914x; 1.0192x over previous
#include <cuda_runtime.h>
#include <cuda_bf16.h>
#include <math.h>

#define Bv 128
#define Tv 64
#define Cv 66
#define Sv 512
#define Wwin 32
#define G3 1536
#define TENC 63
#define NSTEP 127
#define BG3 (Bv * G3)
#define NTH 512

// dynamic smem layout (relative to 1024-aligned base)
#define OFF_WA 0              // phase-A weights: 4 chunks x {hi 8K, lo 8K} = 64K
#define OFF_WB 65536          // phase-B weights: 64K
#define OFF_AB 131072         // A-operand TRIPLE buffer: 3 x 16K = 48K
#define OFF_GATE 180224       // gate1 scratch
#define SMEM_DYN (OFF_GATE + 2816 + 1024)

// ---------------- device scratch ----------------
__device__ float g_h0[Bv * Sv];
__device__ float g_h1[Bv * Sv];
__device__ float g_hist[NSTEP * Bv * Sv];
__device__ float g_gi0[TENC * BG3];
__device__ float g_gi0d[BG3];
__device__ float g_p_gh0[2][BG3];
__device__ float g_p_gh1[2][BG3];
__device__ float g_p_gi1[2][BG3];
__device__ float g_frame[Bv * Cv];
__device__ unsigned int g_arrive;

__device__ __nv_bfloat16 g_h0hi[Bv * Sv], g_h0lo[Bv * Sv];
__device__ __nv_bfloat16 g_h1hi[Bv * Sv], g_h1lo[Bv * Sv];
__device__ __nv_bfloat16 g_fhi[Bv * 128], g_flo[Bv * 128];
__device__ __nv_bfloat16 g_whh0hi[G3 * Sv], g_whh0lo[G3 * Sv];
__device__ __nv_bfloat16 g_whh1hi[G3 * Sv], g_whh1lo[G3 * Sv];
__device__ __nv_bfloat16 g_wih1hi[G3 * Sv], g_wih1lo[G3 * Sv];
__device__ __nv_bfloat16 g_w0hi[G3 * 128], g_w0lo[G3 * 128];

// ---------------- helpers ----------------
__device__ __forceinline__ unsigned smem_u32(const void *p) {
    unsigned a;
    asm("{ .reg .u64 t; cvta.to.shared.u64 t, %1; cvt.u32.u64 %0, t; }" : "=r"(a) : "l"(p));
    return a;
}
__device__ __forceinline__ void cpa16(unsigned dst, const void *src) {
    asm volatile("cp.async.cg.shared.global [%0], [%1], 16;" :: "r"(dst), "l"(src));
}
__device__ __forceinline__ void cpa_commit() {
    asm volatile("cp.async.commit_group;" ::: "memory");
}
template <int N> __device__ __forceinline__ void cpa_wait() {
    asm volatile("cp.async.wait_group %0;" :: "n"(N) : "memory");
}
#define LDSM4(R, addr) \
    asm volatile("ldmatrix.sync.aligned.m8n8.x4.shared.b16 {%0,%1,%2,%3}, [%4];" \
        : "=r"((R)[0]), "=r"((R)[1]), "=r"((R)[2]), "=r"((R)[3]) : "r"(addr))
#define MMA(D, A, b0, b1) \
    asm volatile("mma.sync.aligned.m16n8k16.row.col.f32.bf16.bf16.f32 " \
        "{%0,%1,%2,%3}, {%4,%5,%6,%7}, {%8,%9}, {%0,%1,%2,%3};" \
        : "+f"((D)[0]), "+f"((D)[1]), "+f"((D)[2]), "+f"((D)[3]) \
        : "r"((A)[0]), "r"((A)[1]), "r"((A)[2]), "r"((A)[3]), "r"(b0), "r"(b1))

__device__ __forceinline__ float sigf(float v) { return 1.f / (1.f + expf(-v)); }
__device__ __forceinline__ float4 ldcg4(const float *p) { return __ldcg((const float4 *)p); }
__device__ __forceinline__ float4 ldg4(const float *p) { return __ldg((const float4 *)p); }
__device__ __forceinline__ float4 add4(float4 a, float4 b) {
    return make_float4(a.x + b.x, a.y + b.y, a.z + b.z, a.w + b.w);
}
__device__ __forceinline__ void split_bf16(float v, __nv_bfloat16 &hi, __nv_bfloat16 &lo) {
    hi = __float2bfloat16(v);
    lo = __float2bfloat16(v - __bfloat162float(hi));
}

// ---------------- grid barrier (PROVEN single-counter) ----------------
__device__ __forceinline__ void gsync(unsigned &tgt, int nblk) {
    __syncthreads();
    tgt += (unsigned)nblk;
    if (threadIdx.x == 0) {
        __threadfence();
        atomicAdd(&g_arrive, 1u);
        while (*(volatile unsigned *)&g_arrive < tgt) { }
        __threadfence();
    }
    __syncthreads();
}

// ---------------- stage a 64x64 bf16 hi/lo tile pair (512 threads) ----------
// swizzled 128B rows: byte = r*128 + ((c ^ (r&7)) << 4)
__device__ __forceinline__ void stage_tile64(unsigned dsthi, unsigned dstlo,
    const __nv_bfloat16 *__restrict__ hi, const __nv_bfloat16 *__restrict__ lo, int ld)
{
    const int t = threadIdx.x;          // 0..511 = 64 rows x 8 col-chunks
    int r = t >> 3, c = t & 7;
    unsigned off = (unsigned)(r * 128) + (unsigned)((c ^ (r & 7)) << 4);
    const int s = r * ld + c * 8;
    cpa16(dsthi + off, hi + s);
    cpa16(dstlo + off, lo + s);
}

// ---------------- HMMA on one K=64 chunk: 16 warps, warp tile m16 x n16 -----
__device__ __forceinline__ void hmma_chunk(unsigned abuf, unsigned wbuf,
                                           int wm, int wn, int lane, float acc[2][4])
{
    const int lr = lane & 15;
    const int lh = lane >> 4;
#pragma unroll
    for (int ks = 0; ks < 4; ks++) {
        unsigned ah[4], al[4], bh[4], bl[4];
        {
            int r = wm * 16 + lr;
            unsigned ad = abuf + r * 128 + ((unsigned)((ks * 2 + lh) ^ (r & 7)) << 4);
            LDSM4(ah, ad);
            LDSM4(al, ad + 8192);
        }
        {
            int r = wn * 16 + lr;
            unsigned bd = wbuf + r * 128 + ((unsigned)((ks * 2 + lh) ^ (r & 7)) << 4);
            LDSM4(bh, bd);
            LDSM4(bl, bd + 8192);
        }
#pragma unroll
        for (int nt = 0; nt < 2; nt++) {
            unsigned h0 = nt ? bh[1] : bh[0], h1 = nt ? bh[3] : bh[2];
            unsigned l0 = nt ? bl[1] : bl[0], l1 = nt ? bl[3] : bl[2];
            MMA(acc[nt], ah, h0, h1);   // hi*hi
            MMA(acc[nt], ah, l0, l1);   // hi*lo
            MMA(acc[nt], al, h0, h1);   // lo*hi
        }
    }
}

__device__ __forceinline__ void epilogue(float acc[2][4], float *__restrict__ Out,
                                         int m0, int n0, int wm, int wn, int lane)
{
    const int r0 = m0 + wm * 16 + (lane >> 2);
    const int cb = n0 + wn * 16 + (lane & 3) * 2;
#pragma unroll
    for (int nt = 0; nt < 2; nt++) {
        float *p = Out + r0 * G3 + cb + nt * 8;
        *(float2 *)p = make_float2(acc[nt][0], acc[nt][1]);
        *(float2 *)(p + 8 * G3) = make_float2(acc[nt][2], acc[nt][3]);
    }
}

// ---------------- 64x64x256 tile, persistent W, triple-buffered A ----------
// One __syncthreads per chunk: the sync at iteration ch guarantees all warps
// finished compute(ch-1) (sole prior reader of buffer (ch+2)%3), so staging
// chunk ch+2 into that buffer after the sync is race-free. Two commit-groups
// in flight; wait<1> (wait<0> on last) before the sync makes chunk ch's data
// globally visible.
__device__ void hmma_tile_p(
    const __nv_bfloat16 *__restrict__ Ahi, const __nv_bfloat16 *__restrict__ Alo,
    int m0, int k0, unsigned wbase, float *__restrict__ Out, int n0,
    unsigned sb)
{
    const int tid = threadIdx.x;
    const int lane = tid & 31;
    const int w = tid >> 5;           // 0..15
    const int wm = w & 3, wn = w >> 2;

    float acc[2][4];
#pragma unroll
    for (int b = 0; b < 2; b++)
#pragma unroll
        for (int c = 0; c < 4; c++) acc[b][c] = 0.f;

    const __nv_bfloat16 *a0 = Ahi + m0 * Sv + k0;
    const __nv_bfloat16 *a1 = Alo + m0 * Sv + k0;

    // prologue: chunks 0 and 1 in flight
    stage_tile64(sb + OFF_AB, sb + OFF_AB + 8192, a0, a1, Sv);
    cpa_commit();
    stage_tile64(sb + OFF_AB + 16384, sb + OFF_AB + 16384 + 8192, a0 + 64, a1 + 64, Sv);
    cpa_commit();
#pragma unroll
    for (int ch = 0; ch < 4; ch++) {
        if (ch < 3) cpa_wait<1>(); else cpa_wait<0>();
        __syncthreads();
        if (ch < 2) {
            unsigned nb = sb + OFF_AB + (unsigned)(((ch + 2) % 3) * 16384);
            stage_tile64(nb, nb + 8192, a0 + (ch + 2) * 64, a1 + (ch + 2) * 64, Sv);
            cpa_commit();
        }
        hmma_chunk(sb + OFF_AB + (unsigned)((ch % 3) * 16384),
                   wbase + (unsigned)(ch * 16384), wm, wn, lane, acc);
    }
    __syncthreads();   // protect AB buffers against the next tile's staging
    epilogue(acc, Out, m0, n0, wm, wn, lane);
}

// ---------------- gi0d tile: K=128 (2 chunks), staged A and W --------------
__device__ void hmma_tile_gi0d(int m0, int n0, unsigned sb)
{
    const int tid = threadIdx.x;
    const int lane = tid & 31;
    const int w = tid >> 5;
    const int wm = w & 3, wn = w >> 2;

    float acc[2][4];
#pragma unroll
    for (int b = 0; b < 2; b++)
#pragma unroll
        for (int c = 0; c < 4; c++) acc[b][c] = 0.f;

#pragma unroll
    for (int ch = 0; ch < 2; ch++) {
        stage_tile64(sb + OFF_AB, sb + OFF_AB + 8192,
                     g_fhi + m0 * 128 + ch * 64, g_flo + m0 * 128 + ch * 64, 128);
        stage_tile64(sb + OFF_AB + 16384, sb + OFF_AB + 16384 + 8192,
                     g_w0hi + n0 * 128 + ch * 64, g_w0lo + n0 * 128 + ch * 64, 128);
        cpa_commit();
        cpa_wait<0>();
        __syncthreads();
        hmma_chunk(sb + OFF_AB, sb + OFF_AB + 16384, wm, wn, lane, acc);
        __syncthreads();
    }
    epilogue(acc, g_gi0d, m0, n0, wm, wn, lane);
}

// ---------------- packed fp32x2 (pre_kernel GEMM) ----------------
__device__ __forceinline__ unsigned long long pack2(float a, float b) {
    unsigned long long r;
    asm("mov.b64 %0, {%1, %2};" : "=l"(r) : "f"(a), "f"(b));
    return r;
}
__device__ __forceinline__ unsigned long long ffma2(
    unsigned long long a, unsigned long long b, unsigned long long c) {
    unsigned long long d;
    asm("fma.rn.f32x2 %0, %1, %2, %3;" : "=l"(d) : "l"(a), "l"(b), "l"(c));
    return d;
}
union F2U { unsigned long long u; float2 f; };

// ---------------- kernel 1: init + encoder gi0 + weight conversions --------
__global__ void __launch_bounds__(256) pre_kernel(
    const float *__restrict__ x,
    const float *__restrict__ Wih0,
    const float *__restrict__ Whh0,
    const float *__restrict__ Whh1,
    const float *__restrict__ Wih1)
{
    __shared__ __align__(16) float shA[32 * 68];
    __shared__ __align__(16) float shW[32 * 68];
    const int tid = threadIdx.x;
    const int bx = blockIdx.x;

    if (bx < 64) {
        for (int i = bx * 256 + tid; i < Bv * Sv; i += 64 * 256) {
            g_h0[i] = 0.f; g_h1[i] = 0.f;
            __nv_bfloat16 z = __float2bfloat16(0.f);
            g_h0hi[i] = z; g_h0lo[i] = z; g_h1hi[i] = z; g_h1lo[i] = z;
        }
    }
    if (bx == 64) {
        for (int i = tid; i < Bv * 128; i += 256) {
            int b = i >> 7, c = i & 127;
            float v = (c < Cv) ? x[b * Tv * Cv + (Tv - 1) * Cv + c] : 0.f;
            __nv_bfloat16 hi, lo;
            split_bf16(v, hi, lo);
            g_fhi[i] = hi; g_flo[i] = lo;
            if (c < Cv) g_frame[b * Cv + c] = v;
        }
        if (tid == 0) g_arrive = 0u;
    }
    {
        const int NW = G3 * Sv;
        const int TOT = 3 * NW + G3 * 128;
        const int stride = gridDim.x * 256;
        for (int i = bx * 256 + tid; i < TOT; i += stride) {
            __nv_bfloat16 hi, lo;
            if (i < NW) {
                split_bf16(__ldg(&Whh0[i]), hi, lo);
                g_whh0hi[i] = hi; g_whh0lo[i] = lo;
            } else if (i < 2 * NW) {
                int j = i - NW;
                split_bf16(__ldg(&Whh1[j]), hi, lo);
                g_whh1hi[j] = hi; g_whh1lo[j] = lo;
            } else if (i < 3 * NW) {
                int j = i - 2 * NW;
                split_bf16(__ldg(&Wih1[j]), hi, lo);
                g_wih1hi[j] = hi; g_wih1lo[j] = lo;
            } else {
                int j = i - 3 * NW;
                int n = j >> 7, k = j & 127;
                float v = (k < Cv) ? __ldg(&Wih0[n * Cv + k]) : 0.f;
                split_bf16(v, hi, lo);
                g_w0hi[j] = hi; g_w0lo[j] = lo;
            }
        }
    }

    // encoder gi0 tile (fp32 full precision)
    const int rt = bx / 24;
    const int nt = bx % 24;
    const int r0 = rt * 64, n0 = nt * 64;
    const int tx = tid & 15, ty = tid >> 4;
    const int lr = tid >> 5, lc = tid & 31;

    unsigned long long acc2[4][2];
#pragma unroll
    for (int i = 0; i < 4; i++) { acc2[i][0] = 0ull; acc2[i][1] = 0ull; }

    for (int kc = 0; kc < Cv; kc += 32) {
        __syncthreads();
#pragma unroll
        for (int it = 0; it < 8; it++) {
            int r = lr + it * 8;
            int kk = kc + lc;
            float av = 0.f, wv = 0.f;
            if (kk < Cv) {
                int rr = r0 + r;
                int t = rr >> 7, b = rr & 127;
                av = __ldg(&x[b * (Tv * Cv) + t * Cv + kk]);
                wv = __ldg(&Wih0[(n0 + r) * Cv + kk]);
            }
            shA[lc * 68 + r] = av;
            shW[lc * 68 + r] = wv;
        }
        __syncthreads();
#pragma unroll
        for (int k = 0; k < 32; ++k) {
            const float4 avv = *(const float4 *)(shA + k * 68 + (ty << 2));
            const ulonglong2 bp = *(const ulonglong2 *)(shW + k * 68 + (tx << 2));
            const unsigned long long q0 = pack2(avv.x, avv.x);
            const unsigned long long q1 = pack2(avv.y, avv.y);
            const unsigned long long q2 = pack2(avv.z, avv.z);
            const unsigned long long q3 = pack2(avv.w, avv.w);
            acc2[0][0] = ffma2(q0, bp.x, acc2[0][0]);
            acc2[0][1] = ffma2(q0, bp.y, acc2[0][1]);
            acc2[1][0] = ffma2(q1, bp.x, acc2[1][0]);
            acc2[1][1] = ffma2(q1, bp.y, acc2[1][1]);
            acc2[2][0] = ffma2(q2, bp.x, acc2[2][0]);
            acc2[2][1] = ffma2(q2, bp.y, acc2[2][1]);
            acc2[3][0] = ffma2(q3, bp.x, acc2[3][0]);
            acc2[3][1] = ffma2(q3, bp.y, acc2[3][1]);
        }
    }
#pragma unroll
    for (int i = 0; i < 4; i++) {
        int rr = r0 + (ty << 2) + i;
        int t = rr >> 7, b = rr & 127;
        F2U u0, u1;
        u0.u = acc2[i][0]; u1.u = acc2[i][1];
        *(float4 *)(&g_gi0[t * BG3 + b * G3 + n0 + (tx << 2)]) =
            make_float4(u0.f.x, u0.f.y, u1.f.x, u1.f.y);
    }
}

// ---------------- kernel 2: persistent RNN, 512 threads, persistent W ------
__global__ void __launch_bounds__(NTH, 1) rnn_kernel(
    const float *__restrict__ bih0, const float *__restrict__ bhh0,
    const float *__restrict__ bih1, const float *__restrict__ bhh1,
    const float *__restrict__ Wt, const float *__restrict__ bt,
    const float *__restrict__ Ws, const float *__restrict__ bs,
    float *__restrict__ out, int nblk)
{
    extern __shared__ char dynraw[];
    char *dyn = (char *)(((unsigned long long)dynraw + 1023) & ~1023ull);
    const unsigned sb = smem_u32(dyn);

    const int bid = blockIdx.x;
    const int tid = threadIdx.x;
    const int nth = nblk * NTH;
    const int gtid = bid * NTH + tid;
    unsigned tgt = 0;

    // ---- per-block fixed tasks (same map as R12/R15) ----
    int a_m0 = 0, a_n0 = 0, a_k0 = 0;
    int b_m0 = 0, b_n0 = 0, b_k0 = 0;
    const __nv_bfloat16 *waHi = 0, *waLo = 0, *wbHi = 0, *wbLo = 0;
    const __nv_bfloat16 *aAhi = 0, *aAlo = 0, *bAhi = 0, *bAlo = 0;
    float *aOut = 0, *bOut = 0;
    const bool has_task = (bid < 144);
    if (bid < 96) {
        int kh = bid / 48, sub = bid % 48;
        a_m0 = (sub / 24) * 64; a_n0 = (sub % 24) * 64; a_k0 = kh * 256;
        waHi = g_whh0hi; waLo = g_whh0lo; aAhi = g_h0hi; aAlo = g_h0lo;
        aOut = g_p_gh0[kh];
        b_m0 = a_m0; b_n0 = a_n0; b_k0 = a_k0;
        wbHi = g_wih1hi; wbLo = g_wih1lo; bAhi = g_h0hi; bAlo = g_h0lo;
        bOut = g_p_gi1[kh];
    } else if (bid < 144) {
        int sub = bid - 96;
        a_m0 = (sub / 24) * 64; a_n0 = (sub % 24) * 64; a_k0 = 0;
        waHi = g_whh1hi; waLo = g_whh1lo; aAhi = g_h1hi; aAlo = g_h1lo;
        aOut = g_p_gh1[0];
        b_m0 = a_m0; b_n0 = a_n0; b_k0 = 256;
        wbHi = g_whh1hi; wbLo = g_whh1lo; bAhi = g_h1hi; bAlo = g_h1lo;
        bOut = g_p_gh1[1];
    }
    const int d_m0 = (bid >= 96 && bid < 144) ? (((bid - 96) / 24) * 64) : 0;
    const int d_n0 = (bid >= 96 && bid < 144) ? (((bid - 96) % 24) * 64) : 0;

    // ---- stage persistent weights (once) ----
    if (has_task) {
#pragma unroll
        for (int c = 0; c < 4; c++) {
            stage_tile64(sb + OFF_WA + c * 16384, sb + OFF_WA + c * 16384 + 8192,
                         waHi + a_n0 * Sv + a_k0 + c * 64,
                         waLo + a_n0 * Sv + a_k0 + c * 64, Sv);
            stage_tile64(sb + OFF_WB + c * 16384, sb + OFF_WB + c * 16384 + 8192,
                         wbHi + b_n0 * Sv + b_k0 + c * 64,
                         wbLo + b_n0 * Sv + b_k0 + c * 64, Sv);
        }
        cpa_commit();
        cpa_wait<0>();
    }
    __syncthreads();

    for (int step = 0; step < NSTEP; step++) {
        const bool dec = (step >= TENC);
        const int d = step - TENC;

        // ======== Phase A: gh0 + gh1-kh0 (persistent W) + [dec] gi0d
        if (has_task) {
            hmma_tile_p(aAhi, aAlo, a_m0, a_k0, sb + OFF_WA, aOut, a_n0, sb);
            if (dec && bid >= 96)
                hmma_tile_gi0d(d_m0, d_n0, sb);
        }
        gsync(tgt, nblk);

        // ======== gate0: h0 update
        {
            const float *GI = dec ? g_gi0d : (g_gi0 + step * BG3);
            for (int g = gtid; g < (Bv * Sv) / 4; g += nth) {
                int v = g << 2;
                int b = v >> 9, s = v & 511;
                const int rb = b * G3 + s;

                float4 ir = add4(ldcg4(GI + rb), ldg4(bih0 + s));
                float4 iz = add4(ldcg4(GI + rb + 512), ldg4(bih0 + 512 + s));
                float4 in_ = add4(ldcg4(GI + rb + 1024), ldg4(bih0 + 1024 + s));
                float4 hr = add4(add4(ldcg4(g_p_gh0[0] + rb), ldcg4(g_p_gh0[1] + rb)),
                                 ldg4(bhh0 + s));
                float4 hz = add4(add4(ldcg4(g_p_gh0[0] + rb + 512), ldcg4(g_p_gh0[1] + rb + 512)),
                                 ldg4(bhh0 + 512 + s));
                float4 hn = add4(add4(ldcg4(g_p_gh0[0] + rb + 1024), ldcg4(g_p_gh0[1] + rb + 1024)),
                                 ldg4(bhh0 + 1024 + s));
                float4 hold = ldcg4(g_h0 + v);

                float irv[4] = {ir.x, ir.y, ir.z, ir.w};
                float izv[4] = {iz.x, iz.y, iz.z, iz.w};
                float inv[4] = {in_.x, in_.y, in_.z, in_.w};
                float hrv[4] = {hr.x, hr.y, hr.z, hr.w};
                float hzv[4] = {hz.x, hz.y, hz.z, hz.w};
                float hnv[4] = {hn.x, hn.y, hn.z, hn.w};
                float hov[4] = {hold.x, hold.y, hold.z, hold.w};
                float res[4];
                __nv_bfloat16 rhi[4], rlo[4];
#pragma unroll
                for (int q = 0; q < 4; q++) {
                    float r = sigf(irv[q] + hrv[q]);
                    float z = sigf(izv[q] + hzv[q]);
                    float n = tanhf(inv[q] + r * hnv[q]);
                    res[q] = (1.f - z) * n + z * hov[q];
                    split_bf16(res[q], rhi[q], rlo[q]);
                }
                *(float4 *)(g_h0 + v) = make_float4(res[0], res[1], res[2], res[3]);
                __nv_bfloat162 *ph = (__nv_bfloat162 *)(g_h0hi + v);
                __nv_bfloat162 *pl = (__nv_bfloat162 *)(g_h0lo + v);
                ph[0] = __nv_bfloat162(rhi[0], rhi[1]);
                ph[1] = __nv_bfloat162(rhi[2], rhi[3]);
                pl[0] = __nv_bfloat162(rlo[0], rlo[1]);
                pl[1] = __nv_bfloat162(rlo[2], rlo[3]);
            }
        }
        gsync(tgt, nblk);

        // ======== Phase B: gi1 + gh1-kh1 (persistent W)
        if (has_task)
            hmma_tile_p(bAhi, bAlo, b_m0, b_k0, sb + OFF_WB, bOut, b_n0, sb);
        gsync(tgt, nblk);

        // ======== gate1 (+ global hist, window) + decoder projection
        if (bid < Bv) {
            const int b = bid;
            float *shT = (float *)(dyn + OFF_GATE);
            float *shR = shT + 512;
            float *shWt = shR + 160;
            if (dec && tid < 32) shWt[tid] = __ldg(&Wt[tid]);
            __syncthreads();
            const float bt0 = __ldg(&bt[0]);

            {
                const int s = tid;     // NTH == Sv: one element per thread
                const int rb = b * G3 + s;
                float ir = __ldg(&bih1[s]) + __ldcg(&g_p_gi1[0][rb]) + __ldcg(&g_p_gi1[1][rb]);
                float iz = __ldg(&bih1[512 + s]) + __ldcg(&g_p_gi1[0][rb + 512]) + __ldcg(&g_p_gi1[1][rb + 512]);
                float in_ = __ldg(&bih1[1024 + s]) + __ldcg(&g_p_gi1[0][rb + 1024]) + __ldcg(&g_p_gi1[1][rb + 1024]);
                float hr = __ldg(&bhh1[s]) + __ldcg(&g_p_gh1[0][rb]) + __ldcg(&g_p_gh1[1][rb]);
                float hz = __ldg(&bhh1[512 + s]) + __ldcg(&g_p_gh1[0][rb + 512]) + __ldcg(&g_p_gh1[1][rb + 512]);
                float hn = __ldg(&bhh1[1024 + s]) + __ldcg(&g_p_gh1[0][rb + 1024]) + __ldcg(&g_p_gh1[1][rb + 1024]);
                float r = sigf(ir + hr);
                float z = sigf(iz + hz);
                float n = tanhf(in_ + r * hn);
                float h1n = (1.f - z) * n + z * g_h1[b * Sv + s];
                g_h1[b * Sv + s] = h1n;
                g_hist[step * (Bv * Sv) + b * Sv + s] = h1n;
                __nv_bfloat16 hh, hl;
                split_bf16(h1n, hh, hl);
                g_h1hi[b * Sv + s] = hh;
                g_h1lo[b * Sv + s] = hl;
                if (dec) {
                    float acc = bt0;
                    const float *hp = g_hist + b * Sv + s;
#pragma unroll
                    for (int w = 0; w < Wwin - 1; w++)
                        acc += shWt[w] * hp[(32 + d + w) * (Bv * Sv)];
                    acc += shWt[Wwin - 1] * h1n;
                    shT[s] = acc;
                }
            }
            if (dec) {
                __syncthreads();
                if (tid < 2 * Cv) {
                    int c = tid >> 1, h = tid & 1;
                    const float *wr = Ws + c * Sv + h * 256;
                    const float *tr = shT + h * 256;
                    float p0 = 0.f, p1 = 0.f, p2 = 0.f, p3 = 0.f;
#pragma unroll 4
                    for (int s = 0; s < 256; s += 4) {
                        p0 += tr[s + 0] * __ldg(&wr[s + 0]);
                        p1 += tr[s + 1] * __ldg(&wr[s + 1]);
                        p2 += tr[s + 2] * __ldg(&wr[s + 2]);
                        p3 += tr[s + 3] * __ldg(&wr[s + 3]);
                    }
                    shR[tid] = (p0 + p1) + (p2 + p3);
                }
                __syncthreads();
                if (tid < Cv) {
                    float ov = shR[2 * tid] + shR[2 * tid + 1] + __ldg(&bs[tid]);
                    float nf = ov + g_frame[b * Cv + tid];
                    out[b * (Tv * Cv) + d * Cv + tid] = nf;
                    g_frame[b * Cv + tid] = nf;
                    __nv_bfloat16 fh, fl;
                    split_bf16(nf, fh, fl);
                    g_fhi[b * 128 + tid] = fh;
                    g_flo[b * 128 + tid] = fl;
                }
            }
        }
        gsync(tgt, nblk);
    }
}

// ---------------- launch ----------------
extern "C" void kernel_launch(void *const *d_in, const int *in_sizes, int n_in,
                              void *d_out, int out_size)
{
    const float *x    = (const float *)d_in[0];
    const float *Wih0 = (const float *)d_in[1];
    const float *Whh0 = (const float *)d_in[2];
    const float *bih0 = (const float *)d_in[3];
    const float *bhh0 = (const float *)d_in[4];
    const float *Wih1 = (const float *)d_in[5];
    const float *Whh1 = (const float *)d_in[6];
    const float *bih1 = (const float *)d_in[7];
    const float *bhh1 = (const float *)d_in[8];
    const float *Wt   = (const float *)d_in[9];
    const float *bt   = (const float *)d_in[10];
    const float *Ws   = (const float *)d_in[11];
    const float *bs   = (const float *)d_in[12];
    float *out = (float *)d_out;

    int dev = 0;
    cudaGetDevice(&dev);
    int nsm = 0;
    cudaDeviceGetAttribute(&nsm, cudaDevAttrMultiProcessorCount, dev);
    if (nsm < 144) nsm = 148;

    cudaFuncSetAttribute(rnn_kernel, cudaFuncAttributeMaxDynamicSharedMemorySize, SMEM_DYN);

    pre_kernel<<<126 * 24, 256>>>(x, Wih0, Whh0, Whh1, Wih1);
    rnn_kernel<<<nsm, NTH, SMEM_DYN>>>(bih0, bhh0, bih1, bhh1,
                                       Wt, bt, Ws, bs, out, nsm);
}